// round 6
// baseline (speedup 1.0000x reference)
#include <cuda_runtime.h>
#include <cstdint>

#define BB 8
#define NN 4096
#define MM 1024
#define KK 32
#define CF 64
#define C0IN 67
#define C0 64
#define C1 64
#define C2 128
#define STOT (BB*MM*KK)          // 262144
#define NPTS (BB*NN)             // 32768
#define NBLK (STOT/256)          // 1024
#define NQ   (BB*MM)             // 8192
#define EPSBN 1e-5f
#define BLKS 256

typedef unsigned long long ull;

// ---------------- scratch ----------------------------------------------------
__device__ int   g_idx[STOT];
__device__ float g_y[(size_t)NPTS*C0];      // per-point MLP0 output [pt][64]
__device__ float g_h0[(size_t)C0*STOT];
__device__ float g_h1[(size_t)C1*STOT];
__device__ float g_ps1[(size_t)C2*NBLK];
__device__ float g_ps2[(size_t)C2*NBLK];
__device__ float g_hmax[(size_t)C2*NQ];
__device__ float g_hmin[(size_t)C2*NQ];
__device__ float g_scale[C2];
__device__ float g_shift[C2];

// ---------------- f32x2 helpers ----------------------------------------------
__device__ __forceinline__ ull ffma2(ull a, ull b, ull c) {
    ull d;
    asm("fma.rn.f32x2 %0, %1, %2, %3;" : "=l"(d) : "l"(a), "l"(b), "l"(c));
    return d;
}
__device__ __forceinline__ ull pack2f(float x, float y) {
    ull d; asm("mov.b64 %0, {%1, %2};" : "=l"(d) : "f"(x), "f"(y)); return d;
}
__device__ __forceinline__ void unpack2(ull a, float& x, float& y) {
    asm("mov.b64 {%0, %1}, %2;" : "=f"(x), "=f"(y) : "l"(a));
}

__global__ void k_copyq(const float* __restrict__ q, float* __restrict__ out) {
    int i = blockIdx.x * 256 + threadIdx.x;
    out[i] = q[i];
}

// ---------------- ball query --------------------------------------------------
__global__ void k_ballquery(const float* __restrict__ p, const float* __restrict__ q) {
    extern __shared__ float sp[];
    int* sfound = (int*)(sp + NN*3);
    const int b    = blockIdx.y;
    const int warp = threadIdx.x >> 5;
    const int lane = threadIdx.x & 31;
    const int m    = blockIdx.x * 8 + warp;

    const float* pb = p + (size_t)b * NN * 3;
    for (int i = threadIdx.x; i < NN*3; i += blockDim.x) sp[i] = pb[i];
    __syncthreads();

    const float qx = q[((size_t)b*MM + m)*3 + 0];
    const float qy = q[((size_t)b*MM + m)*3 + 1];
    const float qz = q[((size_t)b*MM + m)*3 + 2];
    const float R2 = 0.04f;

    int cnt = 0;
    for (int j0 = 0; j0 < NN; j0 += 32) {
        int j = j0 + lane;
        float dx = __fadd_rn(sp[3*j+0], -qx);
        float dy = __fadd_rn(sp[3*j+1], -qy);
        float dz = __fadd_rn(sp[3*j+2], -qz);
        float d2 = __fadd_rn(__fadd_rn(__fmul_rn(dx,dx), __fmul_rn(dy,dy)), __fmul_rn(dz,dz));
        bool in = d2 < R2;
        unsigned bal = __ballot_sync(0xffffffffu, in);
        if (in) {
            int slot = cnt + __popc(bal & ((1u << lane) - 1u));
            if (slot < KK) sfound[warp*KK + slot] = j;
        }
        cnt += __popc(bal);
        if (cnt >= KK) break;
    }
    __syncwarp();
    int v;
    if (lane < cnt)      v = sfound[warp*KK + lane];
    else if (cnt > 0)    v = sfound[warp*KK];
    else                 v = 0;
    g_idx[((size_t)b*MM + m)*KK + lane] = v;
}

// =====================================================================
// GEMM core (64 outs x 256 samples per block; thread = 8 outs x 8 samp)
// =====================================================================
template<int CIN>
__device__ __forceinline__ void gemm_core(
    const ull* __restrict__ Wsm, const float* __restrict__ Ism,
    const float* __restrict__ bias, int co0, ull (&acc)[8][4])
{
    const int tid = threadIdx.x;
    const int og = tid >> 5;
    const int sg = tid & 31;
    const int o_base = og * 8;

#pragma unroll
    for (int o = 0; o < 8; o++) {
        float bv = bias[co0 + o_base + o];
        ull bb = pack2f(bv, bv);
        acc[o][0] = bb; acc[o][1] = bb; acc[o][2] = bb; acc[o][3] = bb;
    }

#pragma unroll 2
    for (int c = 0; c < CIN; c++) {
        const ulonglong2* ip = reinterpret_cast<const ulonglong2*>(Ism + c*BLKS);
        ulonglong2 ia = ip[sg];
        ulonglong2 ib = ip[32 + sg];
        const ulonglong2* wp = reinterpret_cast<const ulonglong2*>(Wsm + c*64 + o_base);
        ulonglong2 w01 = wp[0], w23 = wp[1], w45 = wp[2], w67 = wp[3];
        ull w[8] = {w01.x, w01.y, w23.x, w23.y, w45.x, w45.y, w67.x, w67.y};
#pragma unroll
        for (int o = 0; o < 8; o++) {
            acc[o][0] = ffma2(ia.x, w[o], acc[o][0]);
            acc[o][1] = ffma2(ia.y, w[o], acc[o][1]);
            acc[o][2] = ffma2(ib.x, w[o], acc[o][2]);
            acc[o][3] = ffma2(ib.y, w[o], acc[o][3]);
        }
    }
}

// epilogue: store h + BN partial stats
__device__ __forceinline__ void epi_store_stats(
    ull (&acc)[8][4], float* __restrict__ Hout, int co0, int sBase, int bx)
{
    const int tid = threadIdx.x;
    const int og = tid >> 5;
    const int sg = tid & 31;
    const int o_base = og * 8;

#pragma unroll
    for (int o = 0; o < 8; o++) {
        const int ch = co0 + o_base + o;
        ull* row = reinterpret_cast<ull*>(Hout + (size_t)ch*STOT + sBase);
        reinterpret_cast<ulonglong2*>(row)[sg]      = make_ulonglong2(acc[o][0], acc[o][1]);
        reinterpret_cast<ulonglong2*>(row + 64)[sg] = make_ulonglong2(acc[o][2], acc[o][3]);

        float f0,f1,f2,f3,f4,f5,f6,f7;
        unpack2(acc[o][0], f0, f1);
        unpack2(acc[o][1], f2, f3);
        unpack2(acc[o][2], f4, f5);
        unpack2(acc[o][3], f6, f7);
        float s = ((f0+f1)+(f2+f3)) + ((f4+f5)+(f6+f7));
        float qq = ((f0*f0+f1*f1)+(f2*f2+f3*f3)) + ((f4*f4+f5*f5)+(f6*f6+f7*f7));
#pragma unroll
        for (int d = 16; d; d >>= 1) {
            s  += __shfl_down_sync(0xffffffffu, s,  d);
            qq += __shfl_down_sync(0xffffffffu, qq, d);
        }
        if (sg == 0) {
            g_ps1[(size_t)ch*NBLK + bx] = s;
            g_ps2[(size_t)ch*NBLK + bx] = qq;
        }
    }
}

// epilogue: BN partial stats + per-query max/min (no h store)
__device__ __forceinline__ void epi_stats_maxmin(
    ull (&acc)[8][4], int co0, int bx)
{
    const int tid = threadIdx.x;
    const int og = tid >> 5;
    const int sg = tid & 31;
    const int o_base = og * 8;
    const int qa = sg >> 3;
    const int qb = 4 + qa;

#pragma unroll
    for (int o = 0; o < 8; o++) {
        const int ch = co0 + o_base + o;
        float f0,f1,f2,f3,f4,f5,f6,f7;
        unpack2(acc[o][0], f0, f1);
        unpack2(acc[o][1], f2, f3);
        unpack2(acc[o][2], f4, f5);
        unpack2(acc[o][3], f6, f7);
        float s = ((f0+f1)+(f2+f3)) + ((f4+f5)+(f6+f7));
        float qq = ((f0*f0+f1*f1)+(f2*f2+f3*f3)) + ((f4*f4+f5*f5)+(f6*f6+f7*f7));
        float mxa = fmaxf(fmaxf(f0,f1), fmaxf(f2,f3));
        float mna = fminf(fminf(f0,f1), fminf(f2,f3));
        float mxb = fmaxf(fmaxf(f4,f5), fmaxf(f6,f7));
        float mnb = fminf(fminf(f4,f5), fminf(f6,f7));
#pragma unroll
        for (int d = 16; d; d >>= 1) {
            s  += __shfl_down_sync(0xffffffffu, s,  d);
            qq += __shfl_down_sync(0xffffffffu, qq, d);
        }
#pragma unroll
        for (int d = 4; d; d >>= 1) {
            mxa = fmaxf(mxa, __shfl_down_sync(0xffffffffu, mxa, d, 8));
            mna = fminf(mna, __shfl_down_sync(0xffffffffu, mna, d, 8));
            mxb = fmaxf(mxb, __shfl_down_sync(0xffffffffu, mxb, d, 8));
            mnb = fminf(mnb, __shfl_down_sync(0xffffffffu, mnb, d, 8));
        }
        if (sg == 0) {
            g_ps1[(size_t)ch*NBLK + bx] = s;
            g_ps2[(size_t)ch*NBLK + bx] = qq;
        }
        if ((sg & 7) == 0) {
            g_hmax[(size_t)ch*NQ + bx*8 + qa] = mxa;
            g_hmin[(size_t)ch*NQ + bx*8 + qa] = mna;
            g_hmax[(size_t)ch*NQ + bx*8 + qb] = mxb;
            g_hmin[(size_t)ch*NQ + bx*8 + qb] = mnb;
        }
    }
}

// ---------------- per-point MLP0 x-part: y[pt] = Wx @ x[pt] + b0 ---------------
__global__ void __launch_bounds__(256, 2)
k_pointmlp(const float* __restrict__ x, const float* __restrict__ W,
           const float* __restrict__ bias) {
    extern __shared__ char smemraw[];
    ull*   Wsm = (ull*)smemraw;                 // [64][64] {w,w} (x columns of W0)
    float* Ism = (float*)(Wsm + 64*64);         // [64][256]

    const int tid = threadIdx.x;
    const int ptBase = blockIdx.x * BLKS;
    const int b = ptBase >> 12;                 // 256 | 4096 -> constant per block
    const int nBase = ptBase & 4095;

    for (int i = tid; i < 64*64; i += 256) {
        int c = i >> 6, o = i & 63;
        float w = W[o * C0IN + 3 + c];          // x-feature columns 3..66
        Wsm[i] = pack2f(w, w);
    }
    // stage x: Ism[c][local] = x[b][c][nBase+local]  (coalesced per c)
#pragma unroll 4
    for (int c = 0; c < 64; c++) {
        Ism[c*BLKS + tid] = x[(size_t)b*CF*NN + (size_t)c*NN + nBase + tid];
    }
    __syncthreads();

    ull acc[8][4];
    gemm_core<64>(Wsm, Ism, bias, 0, acc);

    const int og = tid >> 5;
    const int sg = tid & 31;
    const int o_base = og * 8;
#pragma unroll
    for (int k = 0; k < 4; k++) {
        const int la = (k < 2) ? (4*sg + 2*k) : (128 + 4*sg + 2*(k-2));
        float a[8], bb[8];
#pragma unroll
        for (int o = 0; o < 8; o++) unpack2(acc[o][k], a[o], bb[o]);
        float4* d0 = reinterpret_cast<float4*>(g_y + (size_t)(ptBase + la)*64 + o_base);
        d0[0] = make_float4(a[0], a[1], a[2], a[3]);
        d0[1] = make_float4(a[4], a[5], a[6], a[7]);
        float4* d1 = reinterpret_cast<float4*>(g_y + (size_t)(ptBase + la + 1)*64 + o_base);
        d1[0] = make_float4(bb[0], bb[1], bb[2], bb[3]);
        d1[1] = make_float4(bb[4], bb[5], bb[6], bb[7]);
    }
}

// ---------------- layer0 gather: h0[s] = y[idx[s]] + Wp @ (p_j - q_m) ----------
__global__ void __launch_bounds__(256, 2)
k_gather0(const float* __restrict__ p, const float* __restrict__ q,
          const float* __restrict__ W) {
    __shared__ __align__(16) ull   Wp[3*64];        // {w,w} geom weights
    __shared__ int   sj[BLKS];
    __shared__ __align__(16) float sdiff[3*BLKS];

    const int tid = threadIdx.x;
    const int sBase = blockIdx.x * BLKS;

    for (int i = tid; i < 3*64; i += 256) {
        int c = i >> 6, o = i & 63;
        float w = W[o * C0IN + c];                  // geom columns 0..2
        Wp[i] = pack2f(w, w);
    }
    {
        const int s = sBase + tid;
        const int b = s >> 15;
        const int m = (s & 32767) >> 5;
        const int j = g_idx[s];
        sj[tid] = (b << 12) + j;
        const float* qp = q + ((size_t)b*MM + m)*3;
        const float* pp = p + ((size_t)b*NN + j)*3;
        sdiff[0*BLKS + tid] = pp[0] - qp[0];
        sdiff[1*BLKS + tid] = pp[1] - qp[1];
        sdiff[2*BLKS + tid] = pp[2] - qp[2];
    }
    __syncthreads();

    const int og = tid >> 5;
    const int sg = tid & 31;
    const int o_base = og * 8;

    ull acc[8][4];
#pragma unroll
    for (int k = 0; k < 4; k++) {
        const int la = (k < 2) ? (4*sg + 2*k) : (128 + 4*sg + 2*(k-2));
        const int ja = sj[la], jb = sj[la + 1];
        const float4* ya = reinterpret_cast<const float4*>(g_y + (size_t)ja*64 + o_base);
        const float4* yb = reinterpret_cast<const float4*>(g_y + (size_t)jb*64 + o_base);
        float4 a0 = ya[0], a1 = ya[1];
        float4 b0 = yb[0], b1 = yb[1];
        acc[0][k] = pack2f(a0.x, b0.x);
        acc[1][k] = pack2f(a0.y, b0.y);
        acc[2][k] = pack2f(a0.z, b0.z);
        acc[3][k] = pack2f(a0.w, b0.w);
        acc[4][k] = pack2f(a1.x, b1.x);
        acc[5][k] = pack2f(a1.y, b1.y);
        acc[6][k] = pack2f(a1.z, b1.z);
        acc[7][k] = pack2f(a1.w, b1.w);
    }

#pragma unroll
    for (int c = 0; c < 3; c++) {
        const ulonglong2* ip = reinterpret_cast<const ulonglong2*>(sdiff + c*BLKS);
        ulonglong2 ia = ip[sg];
        ulonglong2 ib = ip[32 + sg];
        const ulonglong2* wp = reinterpret_cast<const ulonglong2*>(Wp + c*64 + o_base);
        ulonglong2 w01 = wp[0], w23 = wp[1], w45 = wp[2], w67 = wp[3];
        ull w[8] = {w01.x, w01.y, w23.x, w23.y, w45.x, w45.y, w67.x, w67.y};
#pragma unroll
        for (int o = 0; o < 8; o++) {
            acc[o][0] = ffma2(ia.x, w[o], acc[o][0]);
            acc[o][1] = ffma2(ia.y, w[o], acc[o][1]);
            acc[o][2] = ffma2(ib.x, w[o], acc[o][2]);
            acc[o][3] = ffma2(ib.y, w[o], acc[o][3]);
        }
    }

    epi_store_stats(acc, g_h0, 0, sBase, blockIdx.x);
}

// ---------------- layers 1/2: BN+ReLU staged input, (64 -> 64-out group) ------
template<bool DO_MAX>
__global__ void __launch_bounds__(256, 2)
k_layer(const float* __restrict__ Hin, float* __restrict__ Hout,
        const float* __restrict__ W, const float* __restrict__ bias) {
    extern __shared__ char smemraw[];
    ull*   Wsm = (ull*)smemraw;                 // [64][64] {w,w}
    float* Ism = (float*)(Wsm + 64*64);         // [64][256]
    __shared__ float scs[64], shs[64];

    const int tid = threadIdx.x;
    const int co0 = blockIdx.y * 64;
    const int sBase = blockIdx.x * BLKS;

    if (tid < 64) {
        scs[tid] = g_scale[tid];
        shs[tid] = g_shift[tid];
    }
    for (int i = tid; i < 64*64; i += 256) {
        int c = i >> 6, o = i & 63;
        float w = W[(co0 + o)*64 + c];
        Wsm[i] = pack2f(w, w);
    }
    __syncthreads();

    for (int i = tid; i < 64*64; i += 256) {
        int c = i >> 6, s4 = i & 63;
        float4 v = *reinterpret_cast<const float4*>(Hin + (size_t)c*STOT + sBase + s4*4);
        float sc = scs[c], sh = shs[c];
        v.x = fmaxf(fmaf(v.x, sc, sh), 0.0f);
        v.y = fmaxf(fmaf(v.y, sc, sh), 0.0f);
        v.z = fmaxf(fmaf(v.z, sc, sh), 0.0f);
        v.w = fmaxf(fmaf(v.w, sc, sh), 0.0f);
        *reinterpret_cast<float4*>(Ism + c*BLKS + s4*4) = v;
    }
    __syncthreads();

    ull acc[8][4];
    gemm_core<64>(Wsm, Ism, bias, co0, acc);
    if (DO_MAX)
        epi_stats_maxmin(acc, co0, blockIdx.x);
    else
        epi_store_stats(acc, Hout, co0, sBase, blockIdx.x);
}

// ---------------- final stats reduce ------------------------------------------
__global__ void k_reduce2(const float* __restrict__ gam, const float* __restrict__ bet) {
    __shared__ float s1[256], s2[256];
    const int c = blockIdx.x;
    const int t = threadIdx.x;
    const float* p1 = g_ps1 + (size_t)c*NBLK;
    const float* p2 = g_ps2 + (size_t)c*NBLK;
    float a = ((p1[t] + p1[t+256]) + (p1[t+512] + p1[t+768]));
    float b = ((p2[t] + p2[t+256]) + (p2[t+512] + p2[t+768]));
    s1[t] = a; s2[t] = b;
    __syncthreads();
#pragma unroll
    for (int d = 128; d; d >>= 1) {
        if (t < d) { s1[t] += s1[t+d]; s2[t] += s2[t+d]; }
        __syncthreads();
    }
    if (t == 0) {
        const float inv = 1.0f / (float)STOT;
        float mu  = s1[0] * inv;
        float var = s2[0] * inv - mu * mu;
        float sc  = gam[c] * rsqrtf(var + EPSBN);
        g_scale[c] = sc;
        g_shift[c] = bet[c] - mu * sc;
    }
}

// ---------------- finalize: affine extreme + relu -> out (B,C2,M) -------------
__global__ void k_finalmax(float* __restrict__ out) {
    const int t = blockIdx.x * 256 + threadIdx.x;
    const int m = t & 1023;
    const int c = (t >> 10) & 127;
    const int b = t >> 17;
    const int col = ((b << 7) + (m >> 3)) * 8 + (m & 7);
    const float sc = g_scale[c], sh = g_shift[c];
    float ext = (sc >= 0.0f) ? g_hmax[(size_t)c*NQ + col] : g_hmin[(size_t)c*NQ + col];
    float v = fmaxf(fmaf(ext, sc, sh), 0.0f);
    out[(size_t)BB*MM*3 + (((size_t)b*C2 + c) << 10) + m] = v;
}

// ---------------- launch --------------------------------------------------------
extern "C" void kernel_launch(void* const* d_in, const int* in_sizes, int n_in,
                              void* d_out, int out_size) {
    const float* p   = (const float*)d_in[0];
    const float* q   = (const float*)d_in[1];
    const float* x   = (const float*)d_in[2];
    const float* W0  = (const float*)d_in[3];
    const float* b0  = (const float*)d_in[4];
    const float* g0  = (const float*)d_in[5];
    const float* be0 = (const float*)d_in[6];
    const float* W1  = (const float*)d_in[7];
    const float* b1  = (const float*)d_in[8];
    const float* g1  = (const float*)d_in[9];
    const float* be1 = (const float*)d_in[10];
    const float* W2  = (const float*)d_in[11];
    const float* b2  = (const float*)d_in[12];
    const float* g2  = (const float*)d_in[13];
    const float* be2 = (const float*)d_in[14];
    float* out = (float*)d_out;

    float *h0p, *h1p;
    cudaGetSymbolAddress((void**)&h0p, g_h0);
    cudaGetSymbolAddress((void**)&h1p, g_h1);

    const int bq_smem = NN*3*4 + 8*KK*4;
    const int l_smem  = 64*64*8 + 64*BLKS*4;       // 98304
    cudaFuncSetAttribute(k_ballquery, cudaFuncAttributeMaxDynamicSharedMemorySize, bq_smem);
    cudaFuncSetAttribute(k_pointmlp, cudaFuncAttributeMaxDynamicSharedMemorySize, l_smem);
    cudaFuncSetAttribute(k_layer<false>, cudaFuncAttributeMaxDynamicSharedMemorySize, l_smem);
    cudaFuncSetAttribute(k_layer<true>,  cudaFuncAttributeMaxDynamicSharedMemorySize, l_smem);

    k_copyq<<<(BB*MM*3)/256, 256>>>(q, out);
    k_pointmlp<<<NPTS/BLKS, 256, l_smem>>>(x, W0, b0);
    k_ballquery<<<dim3(MM/8, BB), 256, bq_smem>>>(p, q);

    k_gather0<<<NBLK, 256>>>(p, q, W0);
    k_reduce2<<<C0, 256>>>(g0, be0);

    k_layer<false><<<dim3(NBLK, 1), 256, l_smem>>>(h0p, h1p, W1, b1);
    k_reduce2<<<C1, 256>>>(g1, be1);

    k_layer<true><<<dim3(NBLK, 2), 256, l_smem>>>(h1p, nullptr, W2, b2);
    k_reduce2<<<C2, 256>>>(g2, be2);

    k_finalmax<<<(BB*C2*MM)/256, 256>>>(out);
}

// round 7
// speedup vs baseline: 1.2440x; 1.2440x over previous
#include <cuda_runtime.h>
#include <cstdint>

#define BB 8
#define NN 4096
#define MM 1024
#define KK 32
#define CF 64
#define C0IN 67
#define C0 64
#define C1 64
#define C2 128
#define STOT (BB*MM*KK)          // 262144
#define NBLK (STOT/256)          // 1024
#define NBLK8 (NBLK*8)           // 8192 stat partials per channel
#define NQ   (BB*MM)             // 8192
#define EPSBN 1e-5f
#define BLKS 256

typedef unsigned long long ull;

// ---------------- scratch ----------------------------------------------------
__device__ int   g_idx[STOT];
__device__ float g_xT[BB*NN*CF];
__device__ float g_h0[(size_t)C0*STOT];
__device__ float g_h1[(size_t)C1*STOT];
__device__ float g_ps1[(size_t)C2*NBLK8];
__device__ float g_ps2[(size_t)C2*NBLK8];
__device__ float g_hmax[(size_t)C2*NQ];
__device__ float g_hmin[(size_t)C2*NQ];
__device__ float g_scale[C2];
__device__ float g_shift[C2];

// ---------------- f32x2 helpers ----------------------------------------------
__device__ __forceinline__ ull ffma2(ull a, ull b, ull c) {
    ull d;
    asm("fma.rn.f32x2 %0, %1, %2, %3;" : "=l"(d) : "l"(a), "l"(b), "l"(c));
    return d;
}
__device__ __forceinline__ ull pack2f(float x, float y) {
    ull d; asm("mov.b64 %0, {%1, %2};" : "=l"(d) : "f"(x), "f"(y)); return d;
}
__device__ __forceinline__ void unpack2(ull a, float& x, float& y) {
    asm("mov.b64 {%0, %1}, %2;" : "=f"(x), "=f"(y) : "l"(a));
}

// ---------------- transpose x: (B,C,N) -> (B,N,C) ----------------------------
__global__ void k_transpose(const float* __restrict__ x) {
    __shared__ float t[32][33];
    int b  = blockIdx.z;
    int c0 = blockIdx.y * 32;
    int n0 = blockIdx.x * 32;
    int tx = threadIdx.x, ty = threadIdx.y;
#pragma unroll
    for (int r = ty; r < 32; r += 8)
        t[r][tx] = x[(size_t)b*CF*NN + (size_t)(c0 + r)*NN + n0 + tx];
    __syncthreads();
#pragma unroll
    for (int r = ty; r < 32; r += 8)
        g_xT[((size_t)b*NN + n0 + r)*CF + c0 + tx] = t[tx][r];
}

__global__ void k_copyq(const float* __restrict__ q, float* __restrict__ out) {
    int i = blockIdx.x * 256 + threadIdx.x;
    out[i] = q[i];
}

// ---------------- ball query --------------------------------------------------
__global__ void k_ballquery(const float* __restrict__ p, const float* __restrict__ q) {
    extern __shared__ float sp[];
    int* sfound = (int*)(sp + NN*3);
    const int b    = blockIdx.y;
    const int warp = threadIdx.x >> 5;
    const int lane = threadIdx.x & 31;
    const int m    = blockIdx.x * 8 + warp;

    const float* pb = p + (size_t)b * NN * 3;
    for (int i = threadIdx.x; i < NN*3; i += blockDim.x) sp[i] = pb[i];
    __syncthreads();

    const float qx = q[((size_t)b*MM + m)*3 + 0];
    const float qy = q[((size_t)b*MM + m)*3 + 1];
    const float qz = q[((size_t)b*MM + m)*3 + 2];
    const float R2 = 0.04f;

    int cnt = 0;
    for (int j0 = 0; j0 < NN; j0 += 32) {
        int j = j0 + lane;
        float dx = __fadd_rn(sp[3*j+0], -qx);
        float dy = __fadd_rn(sp[3*j+1], -qy);
        float dz = __fadd_rn(sp[3*j+2], -qz);
        float d2 = __fadd_rn(__fadd_rn(__fmul_rn(dx,dx), __fmul_rn(dy,dy)), __fmul_rn(dz,dz));
        bool in = d2 < R2;
        unsigned bal = __ballot_sync(0xffffffffu, in);
        if (in) {
            int slot = cnt + __popc(bal & ((1u << lane) - 1u));
            if (slot < KK) sfound[warp*KK + slot] = j;
        }
        cnt += __popc(bal);
        if (cnt >= KK) break;
    }
    __syncwarp();
    int v;
    if (lane < cnt)      v = sfound[warp*KK + lane];
    else if (cnt > 0)    v = sfound[warp*KK];
    else                 v = 0;
    g_idx[((size_t)b*MM + m)*KK + lane] = v;
}

// =====================================================================
// GEMM core v2: warp = 32-sample chunk (one query), lane: og=lane>>2,
// sg=lane&3. Thread = 8 outs x 8 consecutive samples. Input loads are
// 8-lane broadcasts (1 wavefront/instr); weights 4-lane broadcasts.
// =====================================================================
template<int CIN>
__device__ __forceinline__ void gemm_core(
    const ull* __restrict__ Wsm, const float* __restrict__ Ism,
    const float* __restrict__ bias, int co0, ull (&acc)[8][4])
{
    const int tid  = threadIdx.x;
    const int ws   = tid >> 5;
    const int lane = tid & 31;
    const int og   = lane >> 2;
    const int sg   = lane & 3;
    const int o_base = og * 8;
    const int sOff = ws*32 + sg*8;

#pragma unroll
    for (int o = 0; o < 8; o++) {
        float bv = bias[co0 + o_base + o];
        ull bb = pack2f(bv, bv);
        acc[o][0] = bb; acc[o][1] = bb; acc[o][2] = bb; acc[o][3] = bb;
    }

#pragma unroll 2
    for (int c = 0; c < CIN; c++) {
        const ulonglong2* ip = reinterpret_cast<const ulonglong2*>(Ism + c*BLKS + sOff);
        ulonglong2 ia = ip[0];     // samples sOff..sOff+3
        ulonglong2 ib = ip[1];     // samples sOff+4..sOff+7
        const ulonglong2* wp = reinterpret_cast<const ulonglong2*>(Wsm + c*64 + o_base);
        ulonglong2 w01 = wp[0], w23 = wp[1], w45 = wp[2], w67 = wp[3];
        ull w[8] = {w01.x, w01.y, w23.x, w23.y, w45.x, w45.y, w67.x, w67.y};
#pragma unroll
        for (int o = 0; o < 8; o++) {
            acc[o][0] = ffma2(ia.x, w[o], acc[o][0]);
            acc[o][1] = ffma2(ia.y, w[o], acc[o][1]);
            acc[o][2] = ffma2(ib.x, w[o], acc[o][2]);
            acc[o][3] = ffma2(ib.y, w[o], acc[o][3]);
        }
    }
}

// epilogue: store h + BN partial stats (per warp-chunk)
__device__ __forceinline__ void epi_store_stats(
    ull (&acc)[8][4], float* __restrict__ Hout, int co0, int sBase, int bx)
{
    const int tid  = threadIdx.x;
    const int ws   = tid >> 5;
    const int lane = tid & 31;
    const int og   = lane >> 2;
    const int sg   = lane & 3;
    const int o_base = og * 8;
    const int sOff = ws*32 + sg*8;

#pragma unroll
    for (int o = 0; o < 8; o++) {
        const int ch = co0 + o_base + o;
        ull* row = reinterpret_cast<ull*>(Hout + (size_t)ch*STOT + sBase + sOff);
        reinterpret_cast<ulonglong2*>(row)[0] = make_ulonglong2(acc[o][0], acc[o][1]);
        reinterpret_cast<ulonglong2*>(row)[1] = make_ulonglong2(acc[o][2], acc[o][3]);

        float f0,f1,f2,f3,f4,f5,f6,f7;
        unpack2(acc[o][0], f0, f1);
        unpack2(acc[o][1], f2, f3);
        unpack2(acc[o][2], f4, f5);
        unpack2(acc[o][3], f6, f7);
        float s = ((f0+f1)+(f2+f3)) + ((f4+f5)+(f6+f7));
        float qq = ((f0*f0+f1*f1)+(f2*f2+f3*f3)) + ((f4*f4+f5*f5)+(f6*f6+f7*f7));
        s  += __shfl_down_sync(0xffffffffu, s,  2, 4);
        qq += __shfl_down_sync(0xffffffffu, qq, 2, 4);
        s  += __shfl_down_sync(0xffffffffu, s,  1, 4);
        qq += __shfl_down_sync(0xffffffffu, qq, 1, 4);
        if (sg == 0) {
            g_ps1[(size_t)ch*NBLK8 + bx*8 + ws] = s;
            g_ps2[(size_t)ch*NBLK8 + bx*8 + ws] = qq;
        }
    }
}

// epilogue: BN partial stats + per-query max/min (warp chunk == one query)
__device__ __forceinline__ void epi_stats_maxmin(
    ull (&acc)[8][4], int co0, int bx)
{
    const int tid  = threadIdx.x;
    const int ws   = tid >> 5;
    const int lane = tid & 31;
    const int og   = lane >> 2;
    const int sg   = lane & 3;
    const int o_base = og * 8;
    const int qidx = bx*8 + ws;          // global query id

#pragma unroll
    for (int o = 0; o < 8; o++) {
        const int ch = co0 + o_base + o;
        float f0,f1,f2,f3,f4,f5,f6,f7;
        unpack2(acc[o][0], f0, f1);
        unpack2(acc[o][1], f2, f3);
        unpack2(acc[o][2], f4, f5);
        unpack2(acc[o][3], f6, f7);
        float s = ((f0+f1)+(f2+f3)) + ((f4+f5)+(f6+f7));
        float qq = ((f0*f0+f1*f1)+(f2*f2+f3*f3)) + ((f4*f4+f5*f5)+(f6*f6+f7*f7));
        float mx = fmaxf(fmaxf(fmaxf(f0,f1), fmaxf(f2,f3)), fmaxf(fmaxf(f4,f5), fmaxf(f6,f7)));
        float mn = fminf(fminf(fminf(f0,f1), fminf(f2,f3)), fminf(fminf(f4,f5), fminf(f6,f7)));
        s  += __shfl_down_sync(0xffffffffu, s,  2, 4);
        qq += __shfl_down_sync(0xffffffffu, qq, 2, 4);
        mx = fmaxf(mx, __shfl_down_sync(0xffffffffu, mx, 2, 4));
        mn = fminf(mn, __shfl_down_sync(0xffffffffu, mn, 2, 4));
        s  += __shfl_down_sync(0xffffffffu, s,  1, 4);
        qq += __shfl_down_sync(0xffffffffu, qq, 1, 4);
        mx = fmaxf(mx, __shfl_down_sync(0xffffffffu, mx, 1, 4));
        mn = fminf(mn, __shfl_down_sync(0xffffffffu, mn, 1, 4));
        if (sg == 0) {
            g_ps1[(size_t)ch*NBLK8 + bx*8 + ws] = s;
            g_ps2[(size_t)ch*NBLK8 + bx*8 + ws] = qq;
            g_hmax[(size_t)ch*NQ + qidx] = mx;
            g_hmin[(size_t)ch*NQ + qidx] = mn;
        }
    }
}

// ---------------- layer 0: gather + (67 -> 64) --------------------------------
__global__ void __launch_bounds__(256, 2)
k_layer0(const float* __restrict__ p, const float* __restrict__ q,
         const float* __restrict__ W, const float* __restrict__ bias) {
    extern __shared__ char smemraw[];
    ull*   Wsm = (ull*)smemraw;                 // [67][64] {w,w}
    float* Ism = (float*)(Wsm + C0IN*64);       // [67][256]

    const int tid = threadIdx.x;
    const int sBase = blockIdx.x * BLKS;

    for (int i = tid; i < C0IN*64; i += 256) {
        int c = i >> 6, o = i & 63;
        float w = W[o * C0IN + c];
        Wsm[i] = pack2f(w, w);
    }
    {
        const int s = sBase + tid;
        const int b = s >> 15;
        const int m = (s & 32767) >> 5;
        const int j = g_idx[s];
        const float* qp = q + ((size_t)b*MM + m)*3;
        const float* pp = p + ((size_t)b*NN + j)*3;
        Ism[0*BLKS + tid] = pp[0] - qp[0];
        Ism[1*BLKS + tid] = pp[1] - qp[1];
        Ism[2*BLKS + tid] = pp[2] - qp[2];
        const float4* xr = reinterpret_cast<const float4*>(g_xT + (((size_t)b*NN + j) << 6));
#pragma unroll
        for (int c4 = 0; c4 < 16; c4++) {
            float4 v = xr[c4];
            Ism[(3 + 4*c4 + 0)*BLKS + tid] = v.x;
            Ism[(3 + 4*c4 + 1)*BLKS + tid] = v.y;
            Ism[(3 + 4*c4 + 2)*BLKS + tid] = v.z;
            Ism[(3 + 4*c4 + 3)*BLKS + tid] = v.w;
        }
    }
    __syncthreads();

    ull acc[8][4];
    gemm_core<C0IN>(Wsm, Ism, bias, 0, acc);
    epi_store_stats(acc, g_h0, 0, sBase, blockIdx.x);
}

// ---------------- layers 1/2: BN+ReLU staged input, (64 -> 64-out group) ------
template<bool DO_MAX>
__global__ void __launch_bounds__(256, 2)
k_layer(const float* __restrict__ Hin, float* __restrict__ Hout,
        const float* __restrict__ W, const float* __restrict__ bias) {
    extern __shared__ char smemraw[];
    ull*   Wsm = (ull*)smemraw;                 // [64][64] {w,w}
    float* Ism = (float*)(Wsm + 64*64);         // [64][256]
    __shared__ float scs[64], shs[64];

    const int tid = threadIdx.x;
    const int co0 = blockIdx.y * 64;
    const int sBase = blockIdx.x * BLKS;

    if (tid < 64) {
        scs[tid] = g_scale[tid];
        shs[tid] = g_shift[tid];
    }
    for (int i = tid; i < 64*64; i += 256) {
        int c = i >> 6, o = i & 63;
        float w = W[(co0 + o)*64 + c];
        Wsm[i] = pack2f(w, w);
    }
    __syncthreads();

    for (int i = tid; i < 64*64; i += 256) {
        int c = i >> 6, s4 = i & 63;
        float4 v = *reinterpret_cast<const float4*>(Hin + (size_t)c*STOT + sBase + s4*4);
        float sc = scs[c], sh = shs[c];
        v.x = fmaxf(fmaf(v.x, sc, sh), 0.0f);
        v.y = fmaxf(fmaf(v.y, sc, sh), 0.0f);
        v.z = fmaxf(fmaf(v.z, sc, sh), 0.0f);
        v.w = fmaxf(fmaf(v.w, sc, sh), 0.0f);
        *reinterpret_cast<float4*>(Ism + c*BLKS + s4*4) = v;
    }
    __syncthreads();

    ull acc[8][4];
    gemm_core<64>(Wsm, Ism, bias, co0, acc);
    if (DO_MAX)
        epi_stats_maxmin(acc, co0, blockIdx.x);
    else
        epi_store_stats(acc, Hout, co0, sBase, blockIdx.x);
}

// ---------------- final stats reduce: 8192 partials -> scale/shift ------------
__global__ void k_reduce2(const float* __restrict__ gam, const float* __restrict__ bet) {
    __shared__ float s1[256], s2[256];
    const int c = blockIdx.x;
    const int t = threadIdx.x;
    const float* p1 = g_ps1 + (size_t)c*NBLK8;
    const float* p2 = g_ps2 + (size_t)c*NBLK8;
    float a = 0.f, b = 0.f;
#pragma unroll
    for (int i = 0; i < NBLK8/256; i++) {
        a += p1[i*256 + t];
        b += p2[i*256 + t];
    }
    s1[t] = a; s2[t] = b;
    __syncthreads();
#pragma unroll
    for (int d = 128; d; d >>= 1) {
        if (t < d) { s1[t] += s1[t+d]; s2[t] += s2[t+d]; }
        __syncthreads();
    }
    if (t == 0) {
        const float inv = 1.0f / (float)STOT;
        float mu  = s1[0] * inv;
        float var = s2[0] * inv - mu * mu;
        float sc  = gam[c] * rsqrtf(var + EPSBN);
        g_scale[c] = sc;
        g_shift[c] = bet[c] - mu * sc;
    }
}

// ---------------- finalize: affine extreme + relu -> out (B,C2,M) -------------
__global__ void k_finalmax(float* __restrict__ out) {
    const int t = blockIdx.x * 256 + threadIdx.x;
    const int m = t & 1023;
    const int c = (t >> 10) & 127;
    const int b = t >> 17;
    const int qidx = (b << 10) + m;
    const float sc = g_scale[c], sh = g_shift[c];
    float ext = (sc >= 0.0f) ? g_hmax[(size_t)c*NQ + qidx] : g_hmin[(size_t)c*NQ + qidx];
    float v = fmaxf(fmaf(ext, sc, sh), 0.0f);
    out[(size_t)BB*MM*3 + (((size_t)b*C2 + c) << 10) + m] = v;
}

// ---------------- launch --------------------------------------------------------
extern "C" void kernel_launch(void* const* d_in, const int* in_sizes, int n_in,
                              void* d_out, int out_size) {
    const float* p   = (const float*)d_in[0];
    const float* q   = (const float*)d_in[1];
    const float* x   = (const float*)d_in[2];
    const float* W0  = (const float*)d_in[3];
    const float* b0  = (const float*)d_in[4];
    const float* g0  = (const float*)d_in[5];
    const float* be0 = (const float*)d_in[6];
    const float* W1  = (const float*)d_in[7];
    const float* b1  = (const float*)d_in[8];
    const float* g1  = (const float*)d_in[9];
    const float* be1 = (const float*)d_in[10];
    const float* W2  = (const float*)d_in[11];
    const float* b2  = (const float*)d_in[12];
    const float* g2  = (const float*)d_in[13];
    const float* be2 = (const float*)d_in[14];
    float* out = (float*)d_out;

    float *h0p, *h1p;
    cudaGetSymbolAddress((void**)&h0p, g_h0);
    cudaGetSymbolAddress((void**)&h1p, g_h1);

    const int bq_smem = NN*3*4 + 8*KK*4;
    const int l0_smem = C0IN*64*8 + C0IN*BLKS*4;   // 102912
    const int l_smem  = 64*64*8   + 64*BLKS*4;     // 98304
    cudaFuncSetAttribute(k_ballquery, cudaFuncAttributeMaxDynamicSharedMemorySize, bq_smem);
    cudaFuncSetAttribute(k_layer0, cudaFuncAttributeMaxDynamicSharedMemorySize, l0_smem);
    cudaFuncSetAttribute(k_layer<false>, cudaFuncAttributeMaxDynamicSharedMemorySize, l_smem);
    cudaFuncSetAttribute(k_layer<true>,  cudaFuncAttributeMaxDynamicSharedMemorySize, l_smem);

    k_transpose<<<dim3(NN/32, CF/32, BB), dim3(32, 8)>>>(x);
    k_copyq<<<(BB*MM*3)/256, 256>>>(q, out);
    k_ballquery<<<dim3(MM/8, BB), 256, bq_smem>>>(p, q);

    k_layer0<<<NBLK, 256, l0_smem>>>(p, q, W0, b0);
    k_reduce2<<<C0, 256>>>(g0, be0);

    k_layer<false><<<dim3(NBLK, 1), 256, l_smem>>>(h0p, h1p, W1, b1);
    k_reduce2<<<C1, 256>>>(g1, be1);

    k_layer<true><<<dim3(NBLK, 2), 256, l_smem>>>(h1p, nullptr, W2, b2);
    k_reduce2<<<C2, 256>>>(g2, be2);

    k_finalmax<<<(BB*C2*MM)/256, 256>>>(out);
}

// round 10
// speedup vs baseline: 1.3620x; 1.0949x over previous
#include <cuda_runtime.h>
#include <cstdint>

#define BB 8
#define NN 4096
#define MM 1024
#define KK 32
#define CF 64
#define C0IN 67
#define C0 64
#define C1 64
#define C2 128
#define STOT (BB*MM*KK)          // 262144
#define NBLK (STOT/256)          // 1024
#define NQ   (BB*MM)             // 8192
#define EPSBN 1e-5f
#define BLKS 256

typedef unsigned long long ull;

// ---------------- scratch ----------------------------------------------------
__device__ int   g_idx[STOT];
__device__ float g_xT[BB*NN*CF];
__device__ float g_h0[(size_t)C0*STOT];
__device__ float g_h1[(size_t)C1*STOT];
__device__ float g_ps1[(size_t)C2*NBLK];
__device__ float g_ps2[(size_t)C2*NBLK];
__device__ float g_hmax[(size_t)C2*NQ];
__device__ float g_hmin[(size_t)C2*NQ];
__device__ float g_scale[C2];
__device__ float g_shift[C2];

// ---------------- f32x2 helpers ----------------------------------------------
__device__ __forceinline__ ull ffma2(ull a, ull b, ull c) {
    ull d;
    asm("fma.rn.f32x2 %0, %1, %2, %3;" : "=l"(d) : "l"(a), "l"(b), "l"(c));
    return d;
}
__device__ __forceinline__ ull pack2f(float x, float y) {
    ull d; asm("mov.b64 %0, {%1, %2};" : "=l"(d) : "f"(x), "f"(y)); return d;
}
__device__ __forceinline__ void unpack2(ull a, float& x, float& y) {
    asm("mov.b64 {%0, %1}, %2;" : "=f"(x), "=f"(y) : "l"(a));
}

// ---------------- transpose x: (B,C,N) -> (B,N,C) ----------------------------
__global__ void k_transpose(const float* __restrict__ x) {
    __shared__ float t[32][33];
    int b  = blockIdx.z;
    int c0 = blockIdx.y * 32;
    int n0 = blockIdx.x * 32;
    int tx = threadIdx.x, ty = threadIdx.y;
#pragma unroll
    for (int r = ty; r < 32; r += 8)
        t[r][tx] = x[(size_t)b*CF*NN + (size_t)(c0 + r)*NN + n0 + tx];
    __syncthreads();
#pragma unroll
    for (int r = ty; r < 32; r += 8)
        g_xT[((size_t)b*NN + n0 + r)*CF + c0 + tx] = t[tx][r];
}

__global__ void k_copyq(const float* __restrict__ q, float* __restrict__ out) {
    int i = blockIdx.x * 256 + threadIdx.x;
    out[i] = q[i];
}

// ---------------- ball query --------------------------------------------------
__global__ void k_ballquery(const float* __restrict__ p, const float* __restrict__ q) {
    extern __shared__ float sp[];
    int* sfound = (int*)(sp + NN*3);
    const int b    = blockIdx.y;
    const int warp = threadIdx.x >> 5;
    const int lane = threadIdx.x & 31;
    const int m    = blockIdx.x * 8 + warp;

    const float* pb = p + (size_t)b * NN * 3;
    for (int i = threadIdx.x; i < NN*3; i += blockDim.x) sp[i] = pb[i];
    __syncthreads();

    const float qx = q[((size_t)b*MM + m)*3 + 0];
    const float qy = q[((size_t)b*MM + m)*3 + 1];
    const float qz = q[((size_t)b*MM + m)*3 + 2];
    const float R2 = 0.04f;

    int cnt = 0;
    for (int j0 = 0; j0 < NN; j0 += 32) {
        int j = j0 + lane;
        float dx = __fadd_rn(sp[3*j+0], -qx);
        float dy = __fadd_rn(sp[3*j+1], -qy);
        float dz = __fadd_rn(sp[3*j+2], -qz);
        float d2 = __fadd_rn(__fadd_rn(__fmul_rn(dx,dx), __fmul_rn(dy,dy)), __fmul_rn(dz,dz));
        bool in = d2 < R2;
        unsigned bal = __ballot_sync(0xffffffffu, in);
        if (in) {
            int slot = cnt + __popc(bal & ((1u << lane) - 1u));
            if (slot < KK) sfound[warp*KK + slot] = j;
        }
        cnt += __popc(bal);
        if (cnt >= KK) break;
    }
    __syncwarp();
    int v;
    if (lane < cnt)      v = sfound[warp*KK + lane];
    else if (cnt > 0)    v = sfound[warp*KK];
    else                 v = 0;
    g_idx[((size_t)b*MM + m)*KK + lane] = v;
}

// =====================================================================
// GEMM core (64 outs x 256 samples per block; thread = 8 outs x 8 samp)
// Pointer-based, unroll-4: immediate-offset LDS within groups.
// =====================================================================
template<int CIN>
__device__ __forceinline__ void gemm_core(
    const ull* __restrict__ Wsm, const float* __restrict__ Ism,
    const float* __restrict__ bias, int co0, ull (&acc)[8][4])
{
    const int tid = threadIdx.x;
    const int og = tid >> 5;
    const int sg = tid & 31;
    const int o_base = og * 8;

#pragma unroll
    for (int o = 0; o < 8; o++) {
        float bv = bias[co0 + o_base + o];
        ull bb = pack2f(bv, bv);
        acc[o][0] = bb; acc[o][1] = bb; acc[o][2] = bb; acc[o][3] = bb;
    }

    // Ism: channel stride = 256 floats = 64 ulonglong2
    // Wsm: channel stride = 64 ull = 32 ulonglong2
    const ulonglong2* ibase = reinterpret_cast<const ulonglong2*>(Ism) + sg;
    const ulonglong2* wbase = reinterpret_cast<const ulonglong2*>(Wsm + o_base);

#pragma unroll 4
    for (int c = 0; c < CIN; c++) {
        ulonglong2 ia = ibase[c*64];            // samples 4sg..4sg+3
        ulonglong2 ib = ibase[c*64 + 32];       // samples 128+4sg..
        ulonglong2 w01 = wbase[c*32];
        ulonglong2 w23 = wbase[c*32 + 1];
        ulonglong2 w45 = wbase[c*32 + 2];
        ulonglong2 w67 = wbase[c*32 + 3];
        ull w[8] = {w01.x, w01.y, w23.x, w23.y, w45.x, w45.y, w67.x, w67.y};
#pragma unroll
        for (int o = 0; o < 8; o++) {
            acc[o][0] = ffma2(ia.x, w[o], acc[o][0]);
            acc[o][1] = ffma2(ia.y, w[o], acc[o][1]);
            acc[o][2] = ffma2(ib.x, w[o], acc[o][2]);
            acc[o][3] = ffma2(ib.y, w[o], acc[o][3]);
        }
    }
}

// epilogue: store h + BN partial stats
__device__ __forceinline__ void epi_store_stats(
    ull (&acc)[8][4], float* __restrict__ Hout, int co0, int sBase, int bx)
{
    const int tid = threadIdx.x;
    const int og = tid >> 5;
    const int sg = tid & 31;
    const int o_base = og * 8;

#pragma unroll
    for (int o = 0; o < 8; o++) {
        const int ch = co0 + o_base + o;
        ull* row = reinterpret_cast<ull*>(Hout + (size_t)ch*STOT + sBase);
        reinterpret_cast<ulonglong2*>(row)[sg]      = make_ulonglong2(acc[o][0], acc[o][1]);
        reinterpret_cast<ulonglong2*>(row + 64)[sg] = make_ulonglong2(acc[o][2], acc[o][3]);

        float f0,f1,f2,f3,f4,f5,f6,f7;
        unpack2(acc[o][0], f0, f1);
        unpack2(acc[o][1], f2, f3);
        unpack2(acc[o][2], f4, f5);
        unpack2(acc[o][3], f6, f7);
        float s = ((f0+f1)+(f2+f3)) + ((f4+f5)+(f6+f7));
        float qq = ((f0*f0+f1*f1)+(f2*f2+f3*f3)) + ((f4*f4+f5*f5)+(f6*f6+f7*f7));
#pragma unroll
        for (int d = 16; d; d >>= 1) {
            s  += __shfl_down_sync(0xffffffffu, s,  d);
            qq += __shfl_down_sync(0xffffffffu, qq, d);
        }
        if (sg == 0) {
            g_ps1[(size_t)ch*NBLK + bx] = s;
            g_ps2[(size_t)ch*NBLK + bx] = qq;
        }
    }
}

// epilogue: BN partial stats + per-query max/min (no h store)
__device__ __forceinline__ void epi_stats_maxmin(
    ull (&acc)[8][4], int co0, int bx)
{
    const int tid = threadIdx.x;
    const int og = tid >> 5;
    const int sg = tid & 31;
    const int o_base = og * 8;
    const int qa = sg >> 3;
    const int qb = 4 + qa;

#pragma unroll
    for (int o = 0; o < 8; o++) {
        const int ch = co0 + o_base + o;
        float f0,f1,f2,f3,f4,f5,f6,f7;
        unpack2(acc[o][0], f0, f1);
        unpack2(acc[o][1], f2, f3);
        unpack2(acc[o][2], f4, f5);
        unpack2(acc[o][3], f6, f7);
        float s = ((f0+f1)+(f2+f3)) + ((f4+f5)+(f6+f7));
        float qq = ((f0*f0+f1*f1)+(f2*f2+f3*f3)) + ((f4*f4+f5*f5)+(f6*f6+f7*f7));
        float mxa = fmaxf(fmaxf(f0,f1), fmaxf(f2,f3));
        float mna = fminf(fminf(f0,f1), fminf(f2,f3));
        float mxb = fmaxf(fmaxf(f4,f5), fmaxf(f6,f7));
        float mnb = fminf(fminf(f4,f5), fminf(f6,f7));
#pragma unroll
        for (int d = 16; d; d >>= 1) {
            s  += __shfl_down_sync(0xffffffffu, s,  d);
            qq += __shfl_down_sync(0xffffffffu, qq, d);
        }
#pragma unroll
        for (int d = 4; d; d >>= 1) {
            mxa = fmaxf(mxa, __shfl_down_sync(0xffffffffu, mxa, d, 8));
            mna = fminf(mna, __shfl_down_sync(0xffffffffu, mna, d, 8));
            mxb = fmaxf(mxb, __shfl_down_sync(0xffffffffu, mxb, d, 8));
            mnb = fminf(mnb, __shfl_down_sync(0xffffffffu, mnb, d, 8));
        }
        if (sg == 0) {
            g_ps1[(size_t)ch*NBLK + bx] = s;
            g_ps2[(size_t)ch*NBLK + bx] = qq;
        }
        if ((sg & 7) == 0) {
            g_hmax[(size_t)ch*NQ + bx*8 + qa] = mxa;
            g_hmin[(size_t)ch*NQ + bx*8 + qa] = mna;
            g_hmax[(size_t)ch*NQ + bx*8 + qb] = mxb;
            g_hmin[(size_t)ch*NQ + bx*8 + qb] = mnb;
        }
    }
}

// ---------------- layer 0: gather + (67 -> 64) --------------------------------
__global__ void __launch_bounds__(256, 2)
k_layer0(const float* __restrict__ p, const float* __restrict__ q,
         const float* __restrict__ W, const float* __restrict__ bias) {
    extern __shared__ char smemraw[];
    ull*   Wsm = (ull*)smemraw;                 // [67][64] {w,w}
    float* Ism = (float*)(Wsm + C0IN*64);       // [67][256]

    const int tid = threadIdx.x;
    const int sBase = blockIdx.x * BLKS;

    for (int i = tid; i < C0IN*64; i += 256) {
        int c = i >> 6, o = i & 63;
        float w = W[o * C0IN + c];
        Wsm[i] = pack2f(w, w);
    }
    {
        const int s = sBase + tid;
        const int b = s >> 15;
        const int m = (s & 32767) >> 5;
        const int j = g_idx[s];
        const float* qp = q + ((size_t)b*MM + m)*3;
        const float* pp = p + ((size_t)b*NN + j)*3;
        Ism[0*BLKS + tid] = pp[0] - qp[0];
        Ism[1*BLKS + tid] = pp[1] - qp[1];
        Ism[2*BLKS + tid] = pp[2] - qp[2];
        const float4* xr = reinterpret_cast<const float4*>(g_xT + (((size_t)b*NN + j) << 6));
#pragma unroll
        for (int c4 = 0; c4 < 16; c4++) {
            float4 v = xr[c4];
            Ism[(3 + 4*c4 + 0)*BLKS + tid] = v.x;
            Ism[(3 + 4*c4 + 1)*BLKS + tid] = v.y;
            Ism[(3 + 4*c4 + 2)*BLKS + tid] = v.z;
            Ism[(3 + 4*c4 + 3)*BLKS + tid] = v.w;
        }
    }
    __syncthreads();

    ull acc[8][4];
    gemm_core<C0IN>(Wsm, Ism, bias, 0, acc);
    epi_store_stats(acc, g_h0, 0, sBase, blockIdx.x);
}

// ---------------- layers 1/2: BN+ReLU staged input, (64 -> 64-out group) ------
template<bool DO_MAX>
__global__ void __launch_bounds__(256, 2)
k_layer(const float* __restrict__ Hin, float* __restrict__ Hout,
        const float* __restrict__ W, const float* __restrict__ bias) {
    extern __shared__ char smemraw[];
    ull*   Wsm = (ull*)smemraw;                 // [64][64] {w,w}
    float* Ism = (float*)(Wsm + 64*64);         // [64][256]
    __shared__ float scs[64], shs[64];

    const int tid = threadIdx.x;
    const int co0 = blockIdx.y * 64;
    const int sBase = blockIdx.x * BLKS;

    if (tid < 64) {
        scs[tid] = g_scale[tid];
        shs[tid] = g_shift[tid];
    }
    for (int i = tid; i < 64*64; i += 256) {
        int c = i >> 6, o = i & 63;
        float w = W[(co0 + o)*64 + c];
        Wsm[i] = pack2f(w, w);
    }
    __syncthreads();

    for (int i = tid; i < 64*64; i += 256) {
        int c = i >> 6, s4 = i & 63;
        float4 v = *reinterpret_cast<const float4*>(Hin + (size_t)c*STOT + sBase + s4*4);
        float sc = scs[c], sh = shs[c];
        v.x = fmaxf(fmaf(v.x, sc, sh), 0.0f);
        v.y = fmaxf(fmaf(v.y, sc, sh), 0.0f);
        v.z = fmaxf(fmaf(v.z, sc, sh), 0.0f);
        v.w = fmaxf(fmaf(v.w, sc, sh), 0.0f);
        *reinterpret_cast<float4*>(Ism + c*BLKS + s4*4) = v;
    }
    __syncthreads();

    ull acc[8][4];
    gemm_core<64>(Wsm, Ism, bias, co0, acc);
    if (DO_MAX)
        epi_stats_maxmin(acc, co0, blockIdx.x);
    else
        epi_store_stats(acc, Hout, co0, sBase, blockIdx.x);
}

// ---------------- final stats reduce ------------------------------------------
__global__ void k_reduce2(const float* __restrict__ gam, const float* __restrict__ bet) {
    __shared__ float s1[256], s2[256];
    const int c = blockIdx.x;
    const int t = threadIdx.x;
    const float* p1 = g_ps1 + (size_t)c*NBLK;
    const float* p2 = g_ps2 + (size_t)c*NBLK;
    float a = ((p1[t] + p1[t+256]) + (p1[t+512] + p1[t+768]));
    float b = ((p2[t] + p2[t+256]) + (p2[t+512] + p2[t+768]));
    s1[t] = a; s2[t] = b;
    __syncthreads();
#pragma unroll
    for (int d = 128; d; d >>= 1) {
        if (t < d) { s1[t] += s1[t+d]; s2[t] += s2[t+d]; }
        __syncthreads();
    }
    if (t == 0) {
        const float inv = 1.0f / (float)STOT;
        float mu  = s1[0] * inv;
        float var = s2[0] * inv - mu * mu;
        float sc  = gam[c] * rsqrtf(var + EPSBN);
        g_scale[c] = sc;
        g_shift[c] = bet[c] - mu * sc;
    }
}

// ---------------- finalize: affine extreme + relu -> out (B,C2,M) -------------
__global__ void k_finalmax(float* __restrict__ out) {
    const int t = blockIdx.x * 256 + threadIdx.x;
    const int m = t & 1023;
    const int c = (t >> 10) & 127;
    const int b = t >> 17;
    const int col = ((b << 7) + (m >> 3)) * 8 + (m & 7);
    const float sc = g_scale[c], sh = g_shift[c];
    float ext = (sc >= 0.0f) ? g_hmax[(size_t)c*NQ + col] : g_hmin[(size_t)c*NQ + col];
    float v = fmaxf(fmaf(ext, sc, sh), 0.0f);
    out[(size_t)BB*MM*3 + (((size_t)b*C2 + c) << 10) + m] = v;
}

// ---------------- launch --------------------------------------------------------
extern "C" void kernel_launch(void* const* d_in, const int* in_sizes, int n_in,
                              void* d_out, int out_size) {
    const float* p   = (const float*)d_in[0];
    const float* q   = (const float*)d_in[1];
    const float* x   = (const float*)d_in[2];
    const float* W0  = (const float*)d_in[3];
    const float* b0  = (const float*)d_in[4];
    const float* g0  = (const float*)d_in[5];
    const float* be0 = (const float*)d_in[6];
    const float* W1  = (const float*)d_in[7];
    const float* b1  = (const float*)d_in[8];
    const float* g1  = (const float*)d_in[9];
    const float* be1 = (const float*)d_in[10];
    const float* W2  = (const float*)d_in[11];
    const float* b2  = (const float*)d_in[12];
    const float* g2  = (const float*)d_in[13];
    const float* be2 = (const float*)d_in[14];
    float* out = (float*)d_out;

    float *h0p, *h1p;
    cudaGetSymbolAddress((void**)&h0p, g_h0);
    cudaGetSymbolAddress((void**)&h1p, g_h1);

    const int bq_smem = NN*3*4 + 8*KK*4;
    const int l0_smem = C0IN*64*8 + C0IN*BLKS*4;   // 102912
    const int l_smem  = 64*64*8   + 64*BLKS*4;     // 98304
    cudaFuncSetAttribute(k_ballquery, cudaFuncAttributeMaxDynamicSharedMemorySize, bq_smem);
    cudaFuncSetAttribute(k_layer0, cudaFuncAttributeMaxDynamicSharedMemorySize, l0_smem);
    cudaFuncSetAttribute(k_layer<false>, cudaFuncAttributeMaxDynamicSharedMemorySize, l_smem);
    cudaFuncSetAttribute(k_layer<true>,  cudaFuncAttributeMaxDynamicSharedMemorySize, l_smem);

    k_transpose<<<dim3(NN/32, CF/32, BB), dim3(32, 8)>>>(x);
    k_copyq<<<(BB*MM*3)/256, 256>>>(q, out);
    k_ballquery<<<dim3(MM/8, BB), 256, bq_smem>>>(p, q);

    k_layer0<<<NBLK, 256, l0_smem>>>(p, q, W0, b0);
    k_reduce2<<<C0, 256>>>(g0, be0);

    k_layer<false><<<dim3(NBLK, 1), 256, l_smem>>>(h0p, h1p, W1, b1);
    k_reduce2<<<C1, 256>>>(g1, be1);

    k_layer<true><<<dim3(NBLK, 2), 256, l_smem>>>(h1p, nullptr, W2, b2);
    k_reduce2<<<C2, 256>>>(g2, be2);

    k_finalmax<<<(BB*C2*MM)/256, 256>>>(out);
}

// round 11
// speedup vs baseline: 1.5595x; 1.1450x over previous
#include <cuda_runtime.h>
#include <cuda_bf16.h>
#include <cstdint>

#define BB 8
#define NN 4096
#define MM 1024
#define KK 32
#define CF 64
#define C0IN 67
#define C0 64
#define C1 64
#define C2 128
#define STOT (BB*MM*KK)          // 262144
#define NBLK (STOT/256)          // 1024 layer0 blocks
#define NMB  (STOT/128)          // 2048 mma blocks
#define PSW  16384               // stat partials per channel
#define NQ   (BB*MM)             // 8192
#define EPSBN 1e-5f
#define BLKS 256

typedef unsigned long long ull;

// ---------------- scratch ----------------------------------------------------
__device__ int   g_idx[STOT];
__device__ float g_xT[BB*NN*CF];
__device__ float g_h0[(size_t)C0*STOT];     // [C][S]
__device__ float g_h1[(size_t)C1*STOT];     // [C][S]
__device__ float g_ps1[(size_t)C2*PSW];
__device__ float g_ps2[(size_t)C2*PSW];
__device__ float g_hmax[(size_t)C2*NQ];
__device__ float g_hmin[(size_t)C2*NQ];
__device__ float g_scale[C2];
__device__ float g_shift[C2];

// ---------------- f32x2 helpers ----------------------------------------------
__device__ __forceinline__ ull ffma2(ull a, ull b, ull c) {
    ull d;
    asm("fma.rn.f32x2 %0, %1, %2, %3;" : "=l"(d) : "l"(a), "l"(b), "l"(c));
    return d;
}
__device__ __forceinline__ ull pack2f(float x, float y) {
    ull d; asm("mov.b64 %0, {%1, %2};" : "=l"(d) : "f"(x), "f"(y)); return d;
}
__device__ __forceinline__ void unpack2(ull a, float& x, float& y) {
    asm("mov.b64 {%0, %1}, %2;" : "=f"(x), "=f"(y) : "l"(a));
}
__device__ __forceinline__ uint32_t smem_u32(const void* p) {
    uint32_t a;
    asm("{ .reg .u64 t; cvta.to.shared.u64 t, %1; cvt.u32.u64 %0, t; }" : "=r"(a) : "l"(p));
    return a;
}

// ---------------- mma helpers --------------------------------------------------
__device__ __forceinline__ void ldmA(uint32_t (&r)[4], uint32_t addr) {
    asm volatile("ldmatrix.sync.aligned.m8n8.x4.trans.shared.b16 {%0,%1,%2,%3}, [%4];"
        : "=r"(r[0]), "=r"(r[1]), "=r"(r[2]), "=r"(r[3]) : "r"(addr));
}
__device__ __forceinline__ void ldmB(uint32_t (&r)[2], uint32_t addr) {
    asm volatile("ldmatrix.sync.aligned.m8n8.x2.shared.b16 {%0,%1}, [%2];"
        : "=r"(r[0]), "=r"(r[1]) : "r"(addr));
}
__device__ __forceinline__ void mma_bf16(float (&c)[4], const uint32_t (&a)[4],
                                         const uint32_t (&b)[2]) {
    asm volatile("mma.sync.aligned.m16n8k16.row.col.f32.bf16.bf16.f32 "
        "{%0,%1,%2,%3}, {%4,%5,%6,%7}, {%8,%9}, {%0,%1,%2,%3};"
        : "+f"(c[0]), "+f"(c[1]), "+f"(c[2]), "+f"(c[3])
        : "r"(a[0]), "r"(a[1]), "r"(a[2]), "r"(a[3]), "r"(b[0]), "r"(b[1]));
}
__device__ __forceinline__ ull pack4bf(float v0, float v1, float v2, float v3) {
    unsigned short u0 = __bfloat16_as_ushort(__float2bfloat16_rn(v0));
    unsigned short u1 = __bfloat16_as_ushort(__float2bfloat16_rn(v1));
    unsigned short u2 = __bfloat16_as_ushort(__float2bfloat16_rn(v2));
    unsigned short u3 = __bfloat16_as_ushort(__float2bfloat16_rn(v3));
    return (ull)u0 | ((ull)u1 << 16) | ((ull)u2 << 32) | ((ull)u3 << 48);
}

// ---------------- transpose x: (B,C,N) -> (B,N,C) ----------------------------
__global__ void k_transpose(const float* __restrict__ x) {
    __shared__ float t[32][33];
    int b  = blockIdx.z;
    int c0 = blockIdx.y * 32;
    int n0 = blockIdx.x * 32;
    int tx = threadIdx.x, ty = threadIdx.y;
#pragma unroll
    for (int r = ty; r < 32; r += 8)
        t[r][tx] = x[(size_t)b*CF*NN + (size_t)(c0 + r)*NN + n0 + tx];
    __syncthreads();
#pragma unroll
    for (int r = ty; r < 32; r += 8)
        g_xT[((size_t)b*NN + n0 + r)*CF + c0 + tx] = t[tx][r];
}

__global__ void k_copyq(const float* __restrict__ q, float* __restrict__ out) {
    int i = blockIdx.x * 256 + threadIdx.x;
    out[i] = q[i];
}

// ---------------- ball query --------------------------------------------------
__global__ void k_ballquery(const float* __restrict__ p, const float* __restrict__ q) {
    extern __shared__ float sp[];
    int* sfound = (int*)(sp + NN*3);
    const int b    = blockIdx.y;
    const int warp = threadIdx.x >> 5;
    const int lane = threadIdx.x & 31;
    const int m    = blockIdx.x * 8 + warp;

    const float* pb = p + (size_t)b * NN * 3;
    for (int i = threadIdx.x; i < NN*3; i += blockDim.x) sp[i] = pb[i];
    __syncthreads();

    const float qx = q[((size_t)b*MM + m)*3 + 0];
    const float qy = q[((size_t)b*MM + m)*3 + 1];
    const float qz = q[((size_t)b*MM + m)*3 + 2];
    const float R2 = 0.04f;

    int cnt = 0;
    for (int j0 = 0; j0 < NN; j0 += 32) {
        int j = j0 + lane;
        float dx = __fadd_rn(sp[3*j+0], -qx);
        float dy = __fadd_rn(sp[3*j+1], -qy);
        float dz = __fadd_rn(sp[3*j+2], -qz);
        float d2 = __fadd_rn(__fadd_rn(__fmul_rn(dx,dx), __fmul_rn(dy,dy)), __fmul_rn(dz,dz));
        bool in = d2 < R2;
        unsigned bal = __ballot_sync(0xffffffffu, in);
        if (in) {
            int slot = cnt + __popc(bal & ((1u << lane) - 1u));
            if (slot < KK) sfound[warp*KK + slot] = j;
        }
        cnt += __popc(bal);
        if (cnt >= KK) break;
    }
    __syncwarp();
    int v;
    if (lane < cnt)      v = sfound[warp*KK + lane];
    else if (cnt > 0)    v = sfound[warp*KK];
    else                 v = 0;
    g_idx[((size_t)b*MM + m)*KK + lane] = v;
}

// ---------------- layer 0: scalar FFMA2 GEMM (R5/R10 config) -------------------
__global__ void __launch_bounds__(256, 2)
k_layer0(const float* __restrict__ p, const float* __restrict__ q,
         const float* __restrict__ W, const float* __restrict__ bias) {
    extern __shared__ char smemraw[];
    ull*   Wsm = (ull*)smemraw;                 // [67][64] {w,w}
    float* Ism = (float*)(Wsm + C0IN*64);       // [67][256]

    const int tid = threadIdx.x;
    const int sBase = blockIdx.x * BLKS;

    for (int i = tid; i < C0IN*64; i += 256) {
        int c = i >> 6, o = i & 63;
        float w = W[o * C0IN + c];
        Wsm[i] = pack2f(w, w);
    }
    {
        const int s = sBase + tid;
        const int b = s >> 15;
        const int m = (s & 32767) >> 5;
        const int j = g_idx[s];
        const float* qp = q + ((size_t)b*MM + m)*3;
        const float* pp = p + ((size_t)b*NN + j)*3;
        Ism[0*BLKS + tid] = pp[0] - qp[0];
        Ism[1*BLKS + tid] = pp[1] - qp[1];
        Ism[2*BLKS + tid] = pp[2] - qp[2];
        const float4* xr = reinterpret_cast<const float4*>(g_xT + (((size_t)b*NN + j) << 6));
#pragma unroll
        for (int c4 = 0; c4 < 16; c4++) {
            float4 v = xr[c4];
            Ism[(3 + 4*c4 + 0)*BLKS + tid] = v.x;
            Ism[(3 + 4*c4 + 1)*BLKS + tid] = v.y;
            Ism[(3 + 4*c4 + 2)*BLKS + tid] = v.z;
            Ism[(3 + 4*c4 + 3)*BLKS + tid] = v.w;
        }
    }
    __syncthreads();

    const int og = tid >> 5;
    const int sg = tid & 31;
    const int o_base = og * 8;

    ull acc[8][4];
#pragma unroll
    for (int o = 0; o < 8; o++) {
        float bv = bias[o_base + o];
        ull bb = pack2f(bv, bv);
        acc[o][0] = bb; acc[o][1] = bb; acc[o][2] = bb; acc[o][3] = bb;
    }

    const ulonglong2* ibase = reinterpret_cast<const ulonglong2*>(Ism) + sg;
    const ulonglong2* wbase = reinterpret_cast<const ulonglong2*>(Wsm + o_base);

#pragma unroll 4
    for (int c = 0; c < C0IN; c++) {
        ulonglong2 ia = ibase[c*64];
        ulonglong2 ib = ibase[c*64 + 32];
        ulonglong2 w01 = wbase[c*32];
        ulonglong2 w23 = wbase[c*32 + 1];
        ulonglong2 w45 = wbase[c*32 + 2];
        ulonglong2 w67 = wbase[c*32 + 3];
        ull w[8] = {w01.x, w01.y, w23.x, w23.y, w45.x, w45.y, w67.x, w67.y};
#pragma unroll
        for (int o = 0; o < 8; o++) {
            acc[o][0] = ffma2(ia.x, w[o], acc[o][0]);
            acc[o][1] = ffma2(ia.y, w[o], acc[o][1]);
            acc[o][2] = ffma2(ib.x, w[o], acc[o][2]);
            acc[o][3] = ffma2(ib.y, w[o], acc[o][3]);
        }
    }

#pragma unroll
    for (int o = 0; o < 8; o++) {
        const int ch = o_base + o;
        ull* row = reinterpret_cast<ull*>(g_h0 + (size_t)ch*STOT + sBase);
        reinterpret_cast<ulonglong2*>(row)[sg]      = make_ulonglong2(acc[o][0], acc[o][1]);
        reinterpret_cast<ulonglong2*>(row + 64)[sg] = make_ulonglong2(acc[o][2], acc[o][3]);

        float f0,f1,f2,f3,f4,f5,f6,f7;
        unpack2(acc[o][0], f0, f1);
        unpack2(acc[o][1], f2, f3);
        unpack2(acc[o][2], f4, f5);
        unpack2(acc[o][3], f6, f7);
        float s = ((f0+f1)+(f2+f3)) + ((f4+f5)+(f6+f7));
        float qq = ((f0*f0+f1*f1)+(f2*f2+f3*f3)) + ((f4*f4+f5*f5)+(f6*f6+f7*f7));
#pragma unroll
        for (int d = 16; d; d >>= 1) {
            s  += __shfl_down_sync(0xffffffffu, s,  d);
            qq += __shfl_down_sync(0xffffffffu, qq, d);
        }
        if (sg == 0) {
            g_ps1[(size_t)ch*PSW + blockIdx.x] = s;
            g_ps2[(size_t)ch*PSW + blockIdx.x] = qq;
        }
    }
}

// =====================================================================
// MMA layers: bf16 split (hh+hl+lh), m16n8k16, fp32 accum.
// Block = 128 samples x NOUT outs; warp = 16-sample m-tile x all outs.
// A staged [c][s] bf16 (ldmatrix x4.trans), B staged [o][c] (x2).
// XOR swizzle keeps ldmatrix conflict-free.
// =====================================================================
template<int NOUT, bool DO_MAX>
__global__ void __launch_bounds__(256, 2)
k_mma(const float* __restrict__ Hin, float* __restrict__ Hout,
      const float* __restrict__ W, const float* __restrict__ bias) {
    extern __shared__ char sm[];
    __nv_bfloat16* Ahi = (__nv_bfloat16*)sm;            // [64][128]
    __nv_bfloat16* Alo = Ahi + 64*128;
    __nv_bfloat16* Bhi = Alo + 64*128;                  // [NOUT][64]
    __nv_bfloat16* Blo = Bhi + NOUT*64;
    float* sbias = (float*)(Blo + NOUT*64);             // NOUT
    float* scs   = sbias + NOUT;                        // 64
    float* shs   = scs + 64;                            // 64
    float* smx   = shs + 64;                            // [8][NOUT] (DO_MAX)
    float* smn   = smx + 8*NOUT;

    const int tid = threadIdx.x;
    const int w = tid >> 5, lane = tid & 31;
    const int bx = blockIdx.x;
    const int sBase = bx * 128;

    if (tid < 64) { scs[tid] = g_scale[tid]; shs[tid] = g_shift[tid]; }
    for (int i = tid; i < NOUT; i += 256) sbias[i] = bias[i];

    // stage B: W[o][c] -> bf16 hi/lo, swizzled rows of 128B
    for (int i = tid; i < NOUT*16; i += 256) {
        int o = i >> 4, c4 = (i & 15) * 4;
        float4 wv = *reinterpret_cast<const float4*>(W + o*64 + c4);
        float h0f = __bfloat162float(__float2bfloat16_rn(wv.x));
        float h1f = __bfloat162float(__float2bfloat16_rn(wv.y));
        float h2f = __bfloat162float(__float2bfloat16_rn(wv.z));
        float h3f = __bfloat162float(__float2bfloat16_rn(wv.w));
        uint32_t off = o*128 + ((((c4 >> 3) ^ (o & 7)) << 4)) + (c4 & 7) * 2;
        *reinterpret_cast<ull*>((char*)Bhi + off) = pack4bf(wv.x, wv.y, wv.z, wv.w);
        *reinterpret_cast<ull*>((char*)Blo + off) =
            pack4bf(wv.x - h0f, wv.y - h1f, wv.z - h2f, wv.w - h3f);
    }

    // stage A: Hin [C][S] -> BN+ReLU -> bf16 hi/lo at [c][s], swizzled rows 256B
    for (int i = tid; i < 64*32; i += 256) {
        int c = i >> 5, s4 = (i & 31) * 4;
        float4 v = *reinterpret_cast<const float4*>(Hin + (size_t)c*STOT + sBase + s4);
        float sc = scs[c], sh = shs[c];
        float v0 = fmaxf(fmaf(v.x, sc, sh), 0.0f);
        float v1 = fmaxf(fmaf(v.y, sc, sh), 0.0f);
        float v2 = fmaxf(fmaf(v.z, sc, sh), 0.0f);
        float v3 = fmaxf(fmaf(v.w, sc, sh), 0.0f);
        float h0f = __bfloat162float(__float2bfloat16_rn(v0));
        float h1f = __bfloat162float(__float2bfloat16_rn(v1));
        float h2f = __bfloat162float(__float2bfloat16_rn(v2));
        float h3f = __bfloat162float(__float2bfloat16_rn(v3));
        uint32_t off = c*256 + ((((s4 >> 3) ^ (c & 7)) << 4)) + (s4 & 7) * 2;
        *reinterpret_cast<ull*>((char*)Ahi + off) = pack4bf(v0, v1, v2, v3);
        *reinterpret_cast<ull*>((char*)Alo + off) =
            pack4bf(v0 - h0f, v1 - h1f, v2 - h2f, v3 - h3f);
    }
    __syncthreads();

    const uint32_t aHiB = smem_u32(Ahi), aLoB = smem_u32(Alo);
    const uint32_t bHiB = smem_u32(Bhi), bLoB = smem_u32(Blo);

    float acc[NOUT/8][4];
#pragma unroll
    for (int nt = 0; nt < NOUT/8; nt++)
#pragma unroll
        for (int j = 0; j < 4; j++) acc[nt][j] = 0.0f;

    // ldmatrix lane roles
    const int Am = lane >> 3, Ar = lane & 7;        // A: matrix, row
    const int sA = w*16 + (Am & 1)*8;               // s offset (mult of 8)
    const int cAadd = (Am >> 1) * 8 + Ar;           // c row within chunk
    const int Bm = (lane & 15) >> 3, Br = lane & 7; // B: matrix, row

#pragma unroll
    for (int k = 0; k < 4; k++) {
        int cA = k*16 + cAadd;
        uint32_t offA = cA*256 + ((((sA >> 3) ^ (cA & 7)) << 4));
        uint32_t ah[4], al[4];
        ldmA(ah, aHiB + offA);
        ldmA(al, aLoB + offA);
        int cB = k*16 + Bm*8;
#pragma unroll
        for (int nt = 0; nt < NOUT/8; nt++) {
            int oRow = nt*8 + Br;
            uint32_t offB = oRow*128 + ((((cB >> 3) ^ (oRow & 7)) << 4));
            uint32_t bh[2], bl[2];
            ldmB(bh, bHiB + offB);
            ldmB(bl, bLoB + offB);
            mma_bf16(acc[nt], ah, bh);
            mma_bf16(acc[nt], ah, bl);
            mma_bf16(acc[nt], al, bh);
        }
    }

    // epilogue: bias + (store h) + stats (+ max/min)
    const int sgrp = lane >> 2;        // 0..7
    const int opair = (lane & 3) * 2;

#pragma unroll
    for (int nt = 0; nt < NOUT/8; nt++) {
        int o0 = nt*8 + opair;
        float d0 = acc[nt][0] + sbias[o0];
        float d1 = acc[nt][1] + sbias[o0+1];
        float d2 = acc[nt][2] + sbias[o0];
        float d3 = acc[nt][3] + sbias[o0+1];

        if (!DO_MAX) {
            int s0 = sBase + w*16 + sgrp;
            Hout[(size_t)o0*STOT + s0]         = d0;
            Hout[(size_t)(o0+1)*STOT + s0]     = d1;
            Hout[(size_t)o0*STOT + s0 + 8]     = d2;
            Hout[(size_t)(o0+1)*STOT + s0 + 8] = d3;
        }

        float ss0 = d0 + d2, ss1 = d1 + d3;
        float qq0 = d0*d0 + d2*d2, qq1 = d1*d1 + d3*d3;
        float mx0 = fmaxf(d0, d2), mx1 = fmaxf(d1, d3);
        float mn0 = fminf(d0, d2), mn1 = fminf(d1, d3);
#pragma unroll
        for (int d = 16; d >= 4; d >>= 1) {
            ss0 += __shfl_down_sync(0xffffffffu, ss0, d);
            ss1 += __shfl_down_sync(0xffffffffu, ss1, d);
            qq0 += __shfl_down_sync(0xffffffffu, qq0, d);
            qq1 += __shfl_down_sync(0xffffffffu, qq1, d);
            if (DO_MAX) {
                mx0 = fmaxf(mx0, __shfl_down_sync(0xffffffffu, mx0, d));
                mx1 = fmaxf(mx1, __shfl_down_sync(0xffffffffu, mx1, d));
                mn0 = fminf(mn0, __shfl_down_sync(0xffffffffu, mn0, d));
                mn1 = fminf(mn1, __shfl_down_sync(0xffffffffu, mn1, d));
            }
        }
        if (lane < 4) {
            int ch = nt*8 + lane*2;
            g_ps1[(size_t)ch*PSW + bx*8 + w]     = ss0;
            g_ps1[(size_t)(ch+1)*PSW + bx*8 + w] = ss1;
            g_ps2[(size_t)ch*PSW + bx*8 + w]     = qq0;
            g_ps2[(size_t)(ch+1)*PSW + bx*8 + w] = qq1;
            if (DO_MAX) {
                smx[w*NOUT + ch]   = mx0;
                smx[w*NOUT + ch+1] = mx1;
                smn[w*NOUT + ch]   = mn0;
                smn[w*NOUT + ch+1] = mn1;
            }
        }
    }

    if (DO_MAX) {
        __syncthreads();
        for (int i = tid; i < NOUT*4; i += 256) {
            int ch = i & (NOUT - 1);
            int qj = i / NOUT;                      // 0..3
            float mx = fmaxf(smx[(2*qj)*NOUT + ch], smx[(2*qj+1)*NOUT + ch]);
            float mn = fminf(smn[(2*qj)*NOUT + ch], smn[(2*qj+1)*NOUT + ch]);
            g_hmax[(size_t)ch*NQ + bx*4 + qj] = mx;
            g_hmin[(size_t)ch*NQ + bx*4 + qj] = mn;
        }
    }
}

// ---------------- stats reduce ------------------------------------------------
__global__ void k_reduce2(const float* __restrict__ gam, const float* __restrict__ bet,
                          int count) {
    __shared__ float s1[256], s2[256];
    const int c = blockIdx.x;
    const int t = threadIdx.x;
    const float* p1 = g_ps1 + (size_t)c*PSW;
    const float* p2 = g_ps2 + (size_t)c*PSW;
    float a = 0.f, b = 0.f;
    for (int i = t; i < count; i += 256) { a += p1[i]; b += p2[i]; }
    s1[t] = a; s2[t] = b;
    __syncthreads();
#pragma unroll
    for (int d = 128; d; d >>= 1) {
        if (t < d) { s1[t] += s1[t+d]; s2[t] += s2[t+d]; }
        __syncthreads();
    }
    if (t == 0) {
        const float inv = 1.0f / (float)STOT;
        float mu  = s1[0] * inv;
        float var = s2[0] * inv - mu * mu;
        float sc  = gam[c] * rsqrtf(var + EPSBN);
        g_scale[c] = sc;
        g_shift[c] = bet[c] - mu * sc;
    }
}

// ---------------- finalize: affine extreme + relu -> out (B,C2,M) -------------
__global__ void k_finalmax(float* __restrict__ out) {
    const int t = blockIdx.x * 256 + threadIdx.x;
    const int m = t & 1023;
    const int c = (t >> 10) & 127;
    const int b = t >> 17;
    const int qidx = (b << 10) + m;
    const float sc = g_scale[c], sh = g_shift[c];
    float ext = (sc >= 0.0f) ? g_hmax[(size_t)c*NQ + qidx] : g_hmin[(size_t)c*NQ + qidx];
    float v = fmaxf(fmaf(ext, sc, sh), 0.0f);
    out[(size_t)BB*MM*3 + (((size_t)b*C2 + c) << 10) + m] = v;
}

// ---------------- launch --------------------------------------------------------
extern "C" void kernel_launch(void* const* d_in, const int* in_sizes, int n_in,
                              void* d_out, int out_size) {
    const float* p   = (const float*)d_in[0];
    const float* q   = (const float*)d_in[1];
    const float* x   = (const float*)d_in[2];
    const float* W0  = (const float*)d_in[3];
    const float* b0  = (const float*)d_in[4];
    const float* g0  = (const float*)d_in[5];
    const float* be0 = (const float*)d_in[6];
    const float* W1  = (const float*)d_in[7];
    const float* b1  = (const float*)d_in[8];
    const float* g1  = (const float*)d_in[9];
    const float* be1 = (const float*)d_in[10];
    const float* W2  = (const float*)d_in[11];
    const float* b2  = (const float*)d_in[12];
    const float* g2  = (const float*)d_in[13];
    const float* be2 = (const float*)d_in[14];
    float* out = (float*)d_out;

    float *h0p, *h1p;
    cudaGetSymbolAddress((void**)&h0p, g_h0);
    cudaGetSymbolAddress((void**)&h1p, g_h1);

    const int bq_smem = NN*3*4 + 8*KK*4;
    const int l0_smem = C0IN*64*8 + C0IN*BLKS*4;                 // 102912
    // mma smem: A(2*16KB) + B(2*NOUT*64*2) + bias/scale + maxmin
    const int m1_smem = 2*64*128*2 + 2*64*64*2 + (64+128)*4 + 2*8*64*4;
    const int m2_smem = 2*64*128*2 + 2*128*64*2 + (128+128)*4 + 2*8*128*4;
    cudaFuncSetAttribute(k_ballquery, cudaFuncAttributeMaxDynamicSharedMemorySize, bq_smem);
    cudaFuncSetAttribute(k_layer0, cudaFuncAttributeMaxDynamicSharedMemorySize, l0_smem);
    cudaFuncSetAttribute((const void*)k_mma<64,false>,  cudaFuncAttributeMaxDynamicSharedMemorySize, m1_smem);
    cudaFuncSetAttribute((const void*)k_mma<128,true>,  cudaFuncAttributeMaxDynamicSharedMemorySize, m2_smem);

    k_transpose<<<dim3(NN/32, CF/32, BB), dim3(32, 8)>>>(x);
    k_copyq<<<(BB*MM*3)/256, 256>>>(q, out);
    k_ballquery<<<dim3(MM/8, BB), 256, bq_smem>>>(p, q);

    k_layer0<<<NBLK, 256, l0_smem>>>(p, q, W0, b0);
    k_reduce2<<<C0, 256>>>(g0, be0, NBLK);

    k_mma<64,false><<<NMB, 256, m1_smem>>>(h0p, h1p, W1, b1);
    k_reduce2<<<C1, 256>>>(g1, be1, PSW);

    k_mma<128,true><<<NMB, 256, m2_smem>>>(h1p, nullptr, W2, b2);
    k_reduce2<<<C2, 256>>>(g2, be2, PSW);

    k_finalmax<<<(BB*C2*MM)/256, 256>>>(out);
}

// round 12
// speedup vs baseline: 1.5796x; 1.0129x over previous
#include <cuda_runtime.h>
#include <cuda_bf16.h>
#include <cstdint>

#define BB 8
#define NN 4096
#define MM 1024
#define KK 32
#define CF 64
#define C0IN 67
#define C0 64
#define C1 64
#define C2 128
#define STOT (BB*MM*KK)          // 262144
#define NMB  (STOT/128)          // 2048 mma blocks
#define PSW  16384               // stat partials per channel
#define NQ   (BB*MM)             // 8192
#define EPSBN 1e-5f

typedef unsigned long long ull;

// ---------------- scratch ----------------------------------------------------
__device__ int   g_idx[STOT];
__device__ float g_xT[BB*NN*CF];
__device__ float g_h0[(size_t)C0*STOT];     // [C][S]
__device__ float g_h1[(size_t)C1*STOT];     // [C][S]
__device__ float g_ps1[(size_t)C2*PSW];
__device__ float g_ps2[(size_t)C2*PSW];
__device__ float g_hmax[(size_t)C2*NQ];
__device__ float g_hmin[(size_t)C2*NQ];
__device__ float g_scale[C2];
__device__ float g_shift[C2];

__device__ __forceinline__ uint32_t smem_u32(const void* p) {
    uint32_t a;
    asm("{ .reg .u64 t; cvta.to.shared.u64 t, %1; cvt.u32.u64 %0, t; }" : "=r"(a) : "l"(p));
    return a;
}

// ---------------- mma helpers --------------------------------------------------
__device__ __forceinline__ void ldmA(uint32_t (&r)[4], uint32_t addr) {
    asm volatile("ldmatrix.sync.aligned.m8n8.x4.trans.shared.b16 {%0,%1,%2,%3}, [%4];"
        : "=r"(r[0]), "=r"(r[1]), "=r"(r[2]), "=r"(r[3]) : "r"(addr));
}
__device__ __forceinline__ void ldmB(uint32_t (&r)[2], uint32_t addr) {
    asm volatile("ldmatrix.sync.aligned.m8n8.x2.shared.b16 {%0,%1}, [%2];"
        : "=r"(r[0]), "=r"(r[1]) : "r"(addr));
}
__device__ __forceinline__ void mma_bf16(float (&c)[4], const uint32_t (&a)[4],
                                         const uint32_t (&b)[2]) {
    asm volatile("mma.sync.aligned.m16n8k16.row.col.f32.bf16.bf16.f32 "
        "{%0,%1,%2,%3}, {%4,%5,%6,%7}, {%8,%9}, {%0,%1,%2,%3};"
        : "+f"(c[0]), "+f"(c[1]), "+f"(c[2]), "+f"(c[3])
        : "r"(a[0]), "r"(a[1]), "r"(a[2]), "r"(a[3]), "r"(b[0]), "r"(b[1]));
}
__device__ __forceinline__ ull pack4bf(float v0, float v1, float v2, float v3) {
    unsigned short u0 = __bfloat16_as_ushort(__float2bfloat16_rn(v0));
    unsigned short u1 = __bfloat16_as_ushort(__float2bfloat16_rn(v1));
    unsigned short u2 = __bfloat16_as_ushort(__float2bfloat16_rn(v2));
    unsigned short u3 = __bfloat16_as_ushort(__float2bfloat16_rn(v3));
    return (ull)u0 | ((ull)u1 << 16) | ((ull)u2 << 32) | ((ull)u3 << 48);
}
// elementwise hi/lo split store into [row][128-col] bf16 tile, 256B swizzled rows
__device__ __forceinline__ void splitA(char* hi, char* lo, int r, int s, float v) {
    __nv_bfloat16 h = __float2bfloat16_rn(v);
    float hf = __bfloat162float(h);
    uint32_t off = r*256 + ((((s >> 3) ^ (r & 7)) << 4)) + (s & 7) * 2;
    *reinterpret_cast<__nv_bfloat16*>(hi + off) = h;
    *reinterpret_cast<__nv_bfloat16*>(lo + off) = __float2bfloat16_rn(v - hf);
}

// ---------------- transpose x: (B,C,N) -> (B,N,C) ----------------------------
__global__ void k_transpose(const float* __restrict__ x) {
    __shared__ float t[32][33];
    int b  = blockIdx.z;
    int c0 = blockIdx.y * 32;
    int n0 = blockIdx.x * 32;
    int tx = threadIdx.x, ty = threadIdx.y;
#pragma unroll
    for (int r = ty; r < 32; r += 8)
        t[r][tx] = x[(size_t)b*CF*NN + (size_t)(c0 + r)*NN + n0 + tx];
    __syncthreads();
#pragma unroll
    for (int r = ty; r < 32; r += 8)
        g_xT[((size_t)b*NN + n0 + r)*CF + c0 + tx] = t[tx][r];
}

__global__ void k_copyq(const float* __restrict__ q, float* __restrict__ out) {
    int i = blockIdx.x * 256 + threadIdx.x;
    out[i] = q[i];
}

// ---------------- ball query --------------------------------------------------
__global__ void k_ballquery(const float* __restrict__ p, const float* __restrict__ q) {
    extern __shared__ float sp[];
    int* sfound = (int*)(sp + NN*3);
    const int b    = blockIdx.y;
    const int warp = threadIdx.x >> 5;
    const int lane = threadIdx.x & 31;
    const int m    = blockIdx.x * 8 + warp;

    const float* pb = p + (size_t)b * NN * 3;
    for (int i = threadIdx.x; i < NN*3; i += blockDim.x) sp[i] = pb[i];
    __syncthreads();

    const float qx = q[((size_t)b*MM + m)*3 + 0];
    const float qy = q[((size_t)b*MM + m)*3 + 1];
    const float qz = q[((size_t)b*MM + m)*3 + 2];
    const float R2 = 0.04f;

    int cnt = 0;
    for (int j0 = 0; j0 < NN; j0 += 32) {
        int j = j0 + lane;
        float dx = __fadd_rn(sp[3*j+0], -qx);
        float dy = __fadd_rn(sp[3*j+1], -qy);
        float dz = __fadd_rn(sp[3*j+2], -qz);
        float d2 = __fadd_rn(__fadd_rn(__fmul_rn(dx,dx), __fmul_rn(dy,dy)), __fmul_rn(dz,dz));
        bool in = d2 < R2;
        unsigned bal = __ballot_sync(0xffffffffu, in);
        if (in) {
            int slot = cnt + __popc(bal & ((1u << lane) - 1u));
            if (slot < KK) sfound[warp*KK + slot] = j;
        }
        cnt += __popc(bal);
        if (cnt >= KK) break;
    }
    __syncwarp();
    int v;
    if (lane < cnt)      v = sfound[warp*KK + lane];
    else if (cnt > 0)    v = sfound[warp*KK];
    else                 v = 0;
    g_idx[((size_t)b*MM + m)*KK + lane] = v;
}

// =====================================================================
// Shared MMA epilogue: bias + optional h store + stats (+ max/min)
// =====================================================================
template<int NOUT, bool DO_MAX>
__device__ __forceinline__ void mma_epilogue(
    float (&acc)[NOUT/8][4], const float* sbias, float* smx, float* smn,
    float* __restrict__ Hout, int bx)
{
    const int tid = threadIdx.x;
    const int w = tid >> 5, lane = tid & 31;
    const int sBase = bx * 128;
    const int sgrp = lane >> 2;
    const int opair = (lane & 3) * 2;

#pragma unroll
    for (int nt = 0; nt < NOUT/8; nt++) {
        int o0 = nt*8 + opair;
        float d0 = acc[nt][0] + sbias[o0];
        float d1 = acc[nt][1] + sbias[o0+1];
        float d2 = acc[nt][2] + sbias[o0];
        float d3 = acc[nt][3] + sbias[o0+1];

        if (!DO_MAX) {
            int s0 = sBase + w*16 + sgrp;
            Hout[(size_t)o0*STOT + s0]         = d0;
            Hout[(size_t)(o0+1)*STOT + s0]     = d1;
            Hout[(size_t)o0*STOT + s0 + 8]     = d2;
            Hout[(size_t)(o0+1)*STOT + s0 + 8] = d3;
        }

        float ss0 = d0 + d2, ss1 = d1 + d3;
        float qq0 = d0*d0 + d2*d2, qq1 = d1*d1 + d3*d3;
        float mx0 = fmaxf(d0, d2), mx1 = fmaxf(d1, d3);
        float mn0 = fminf(d0, d2), mn1 = fminf(d1, d3);
#pragma unroll
        for (int d = 16; d >= 4; d >>= 1) {
            ss0 += __shfl_down_sync(0xffffffffu, ss0, d);
            ss1 += __shfl_down_sync(0xffffffffu, ss1, d);
            qq0 += __shfl_down_sync(0xffffffffu, qq0, d);
            qq1 += __shfl_down_sync(0xffffffffu, qq1, d);
            if (DO_MAX) {
                mx0 = fmaxf(mx0, __shfl_down_sync(0xffffffffu, mx0, d));
                mx1 = fmaxf(mx1, __shfl_down_sync(0xffffffffu, mx1, d));
                mn0 = fminf(mn0, __shfl_down_sync(0xffffffffu, mn0, d));
                mn1 = fminf(mn1, __shfl_down_sync(0xffffffffu, mn1, d));
            }
        }
        if (lane < 4) {
            int ch = nt*8 + lane*2;
            g_ps1[(size_t)ch*PSW + bx*8 + w]     = ss0;
            g_ps1[(size_t)(ch+1)*PSW + bx*8 + w] = ss1;
            g_ps2[(size_t)ch*PSW + bx*8 + w]     = qq0;
            g_ps2[(size_t)(ch+1)*PSW + bx*8 + w] = qq1;
            if (DO_MAX) {
                smx[w*NOUT + ch]   = mx0;
                smx[w*NOUT + ch+1] = mx1;
                smn[w*NOUT + ch]   = mn0;
                smn[w*NOUT + ch+1] = mn1;
            }
        }
    }

    if (DO_MAX) {
        __syncthreads();
        for (int i = tid; i < NOUT*4; i += 256) {
            int ch = i & (NOUT - 1);
            int qj = i / NOUT;
            float mx = fmaxf(smx[(2*qj)*NOUT + ch], smx[(2*qj+1)*NOUT + ch]);
            float mn = fminf(smn[(2*qj)*NOUT + ch], smn[(2*qj+1)*NOUT + ch]);
            g_hmax[(size_t)ch*NQ + bx*4 + qj] = mx;
            g_hmin[(size_t)ch*NQ + bx*4 + qj] = mn;
        }
    }
}

// =====================================================================
// layer 0 MMA: gather(67ch) -> 64 outs, K padded to 80 (5 k16-chunks)
// A: [80][128] bf16 hi/lo, 256B swizzled rows. B: [64][128] 256B rows.
// =====================================================================
__global__ void __launch_bounds__(256, 2)
k_mma0(const float* __restrict__ p, const float* __restrict__ q,
       const float* __restrict__ W, const float* __restrict__ bias) {
    extern __shared__ char sm[];
    char* Ahi = sm;                         // [80][128] bf16 (20480B)
    char* Alo = Ahi + 80*256;
    char* Bhi = Alo + 80*256;               // [64][128] bf16 (16384B)
    char* Blo = Bhi + 64*256;
    float* sbias = (float*)(Blo + 64*256);

    const int tid = threadIdx.x;
    const int w = tid >> 5, lane = tid & 31;
    const int bx = blockIdx.x;
    const int sBase = bx * 128;

    if (tid < 64) sbias[tid] = bias[tid];

    // stage B: W0[o][c] (stride 67), pad c 67..127 with zeros
    for (int i = tid; i < 64*128; i += 256) {
        int o = i >> 7, c = i & 127;
        float v = (c < C0IN) ? W[o*C0IN + c] : 0.0f;
        __nv_bfloat16 h = __float2bfloat16_rn(v);
        float hf = __bfloat162float(h);
        uint32_t off = o*256 + ((((c >> 3) ^ (o & 7)) << 4)) + (c & 7) * 2;
        *reinterpret_cast<__nv_bfloat16*>(Bhi + off) = h;
        *reinterpret_cast<__nv_bfloat16*>(Blo + off) = __float2bfloat16_rn(v - hf);
    }
    // zero-pad A rows 67..79
    for (int i = tid; i < 13*128; i += 256) {
        int r = 67 + (i >> 7), s = i & 127;
        uint32_t off = r*256 + ((((s >> 3) ^ (r & 7)) << 4)) + (s & 7) * 2;
        *reinterpret_cast<__nv_bfloat16*>(Ahi + off) = __float2bfloat16_rn(0.0f);
        *reinterpret_cast<__nv_bfloat16*>(Alo + off) = __float2bfloat16_rn(0.0f);
    }
    // stage A: gather; 2 threads per sample (half = channel split)
    {
        const int s = tid & 127;
        const int half = tid >> 7;
        const int gs = sBase + s;
        const int b = gs >> 15;
        const int m = (gs & 32767) >> 5;
        const int j = g_idx[gs];
        const float4* xr = reinterpret_cast<const float4*>(g_xT + (((size_t)b*NN + j) << 6));
        if (half == 0) {
            const float* qp = q + ((size_t)b*MM + m)*3;
            const float* pp = p + ((size_t)b*NN + j)*3;
            splitA(Ahi, Alo, 0, s, pp[0] - qp[0]);
            splitA(Ahi, Alo, 1, s, pp[1] - qp[1]);
            splitA(Ahi, Alo, 2, s, pp[2] - qp[2]);
#pragma unroll
            for (int c4 = 0; c4 < 8; c4++) {
                float4 v = xr[c4];
                splitA(Ahi, Alo, 3 + 4*c4 + 0, s, v.x);
                splitA(Ahi, Alo, 3 + 4*c4 + 1, s, v.y);
                splitA(Ahi, Alo, 3 + 4*c4 + 2, s, v.z);
                splitA(Ahi, Alo, 3 + 4*c4 + 3, s, v.w);
            }
        } else {
#pragma unroll
            for (int c4 = 8; c4 < 16; c4++) {
                float4 v = xr[c4];
                splitA(Ahi, Alo, 3 + 4*c4 + 0, s, v.x);
                splitA(Ahi, Alo, 3 + 4*c4 + 1, s, v.y);
                splitA(Ahi, Alo, 3 + 4*c4 + 2, s, v.z);
                splitA(Ahi, Alo, 3 + 4*c4 + 3, s, v.w);
            }
        }
    }
    __syncthreads();

    const uint32_t aHiB = smem_u32(Ahi), aLoB = smem_u32(Alo);
    const uint32_t bHiB = smem_u32(Bhi), bLoB = smem_u32(Blo);

    float acc[8][4];
#pragma unroll
    for (int nt = 0; nt < 8; nt++)
#pragma unroll
        for (int j = 0; j < 4; j++) acc[nt][j] = 0.0f;

    const int Am = lane >> 3, Ar = lane & 7;
    const int sA = w*16 + (Am & 1)*8;
    const int cAadd = (Am >> 1) * 8 + Ar;
    const int Bm = (lane & 15) >> 3, Br = lane & 7;

#pragma unroll
    for (int k = 0; k < 5; k++) {
        int cA = k*16 + cAadd;
        uint32_t offA = cA*256 + ((((sA >> 3) ^ (cA & 7)) << 4));
        uint32_t ah[4], al[4];
        ldmA(ah, aHiB + offA);
        ldmA(al, aLoB + offA);
        int cB = k*16 + Bm*8;
#pragma unroll
        for (int nt = 0; nt < 8; nt++) {
            int oRow = nt*8 + Br;
            uint32_t offB = oRow*256 + ((((cB >> 3) ^ (oRow & 7)) << 4));
            uint32_t bh[2], bl[2];
            ldmB(bh, bHiB + offB);
            ldmB(bl, bLoB + offB);
            mma_bf16(acc[nt], ah, bh);
            mma_bf16(acc[nt], ah, bl);
            mma_bf16(acc[nt], al, bh);
        }
    }

    mma_epilogue<64, false>(acc, sbias, nullptr, nullptr, g_h0, bx);
}

// =====================================================================
// layers 1/2 MMA: 64 in -> NOUT out, K=64 (4 chunks). A rows 256B, B rows 128B.
// =====================================================================
template<int NOUT, bool DO_MAX>
__global__ void __launch_bounds__(256, 2)
k_mma(const float* __restrict__ Hin, float* __restrict__ Hout,
      const float* __restrict__ W, const float* __restrict__ bias) {
    extern __shared__ char sm[];
    __nv_bfloat16* Ahi = (__nv_bfloat16*)sm;            // [64][128]
    __nv_bfloat16* Alo = Ahi + 64*128;
    __nv_bfloat16* Bhi = Alo + 64*128;                  // [NOUT][64]
    __nv_bfloat16* Blo = Bhi + NOUT*64;
    float* sbias = (float*)(Blo + NOUT*64);             // NOUT
    float* scs   = sbias + NOUT;                        // 64
    float* shs   = scs + 64;                            // 64
    float* smx   = shs + 64;                            // [8][NOUT]
    float* smn   = smx + 8*NOUT;

    const int tid = threadIdx.x;
    const int w = tid >> 5, lane = tid & 31;
    const int bx = blockIdx.x;
    const int sBase = bx * 128;

    if (tid < 64) { scs[tid] = g_scale[tid]; shs[tid] = g_shift[tid]; }
    for (int i = tid; i < NOUT; i += 256) sbias[i] = bias[i];

    for (int i = tid; i < NOUT*16; i += 256) {
        int o = i >> 4, c4 = (i & 15) * 4;
        float4 wv = *reinterpret_cast<const float4*>(W + o*64 + c4);
        float h0f = __bfloat162float(__float2bfloat16_rn(wv.x));
        float h1f = __bfloat162float(__float2bfloat16_rn(wv.y));
        float h2f = __bfloat162float(__float2bfloat16_rn(wv.z));
        float h3f = __bfloat162float(__float2bfloat16_rn(wv.w));
        uint32_t off = o*128 + ((((c4 >> 3) ^ (o & 7)) << 4)) + (c4 & 7) * 2;
        *reinterpret_cast<ull*>((char*)Bhi + off) = pack4bf(wv.x, wv.y, wv.z, wv.w);
        *reinterpret_cast<ull*>((char*)Blo + off) =
            pack4bf(wv.x - h0f, wv.y - h1f, wv.z - h2f, wv.w - h3f);
    }

    for (int i = tid; i < 64*32; i += 256) {
        int c = i >> 5, s4 = (i & 31) * 4;
        float4 v = *reinterpret_cast<const float4*>(Hin + (size_t)c*STOT + sBase + s4);
        float sc = scs[c], sh = shs[c];
        float v0 = fmaxf(fmaf(v.x, sc, sh), 0.0f);
        float v1 = fmaxf(fmaf(v.y, sc, sh), 0.0f);
        float v2 = fmaxf(fmaf(v.z, sc, sh), 0.0f);
        float v3 = fmaxf(fmaf(v.w, sc, sh), 0.0f);
        float h0f = __bfloat162float(__float2bfloat16_rn(v0));
        float h1f = __bfloat162float(__float2bfloat16_rn(v1));
        float h2f = __bfloat162float(__float2bfloat16_rn(v2));
        float h3f = __bfloat162float(__float2bfloat16_rn(v3));
        uint32_t off = c*256 + ((((s4 >> 3) ^ (c & 7)) << 4)) + (s4 & 7) * 2;
        *reinterpret_cast<ull*>((char*)Ahi + off) = pack4bf(v0, v1, v2, v3);
        *reinterpret_cast<ull*>((char*)Alo + off) =
            pack4bf(v0 - h0f, v1 - h1f, v2 - h2f, v3 - h3f);
    }
    __syncthreads();

    const uint32_t aHiB = smem_u32(Ahi), aLoB = smem_u32(Alo);
    const uint32_t bHiB = smem_u32(Bhi), bLoB = smem_u32(Blo);

    float acc[NOUT/8][4];
#pragma unroll
    for (int nt = 0; nt < NOUT/8; nt++)
#pragma unroll
        for (int j = 0; j < 4; j++) acc[nt][j] = 0.0f;

    const int Am = lane >> 3, Ar = lane & 7;
    const int sA = w*16 + (Am & 1)*8;
    const int cAadd = (Am >> 1) * 8 + Ar;
    const int Bm = (lane & 15) >> 3, Br = lane & 7;

#pragma unroll
    for (int k = 0; k < 4; k++) {
        int cA = k*16 + cAadd;
        uint32_t offA = cA*256 + ((((sA >> 3) ^ (cA & 7)) << 4));
        uint32_t ah[4], al[4];
        ldmA(ah, aHiB + offA);
        ldmA(al, aLoB + offA);
        int cB = k*16 + Bm*8;
#pragma unroll
        for (int nt = 0; nt < NOUT/8; nt++) {
            int oRow = nt*8 + Br;
            uint32_t offB = oRow*128 + ((((cB >> 3) ^ (oRow & 7)) << 4));
            uint32_t bh[2], bl[2];
            ldmB(bh, bHiB + offB);
            ldmB(bl, bLoB + offB);
            mma_bf16(acc[nt], ah, bh);
            mma_bf16(acc[nt], ah, bl);
            mma_bf16(acc[nt], al, bh);
        }
    }

    mma_epilogue<NOUT, DO_MAX>(acc, sbias, smx, smn, Hout, bx);
}

// ---------------- stats reduce ------------------------------------------------
__global__ void k_reduce2(const float* __restrict__ gam, const float* __restrict__ bet,
                          int count) {
    __shared__ float s1[256], s2[256];
    const int c = blockIdx.x;
    const int t = threadIdx.x;
    const float* p1 = g_ps1 + (size_t)c*PSW;
    const float* p2 = g_ps2 + (size_t)c*PSW;
    float a = 0.f, b = 0.f;
    for (int i = t; i < count; i += 256) { a += p1[i]; b += p2[i]; }
    s1[t] = a; s2[t] = b;
    __syncthreads();
#pragma unroll
    for (int d = 128; d; d >>= 1) {
        if (t < d) { s1[t] += s1[t+d]; s2[t] += s2[t+d]; }
        __syncthreads();
    }
    if (t == 0) {
        const float inv = 1.0f / (float)STOT;
        float mu  = s1[0] * inv;
        float var = s2[0] * inv - mu * mu;
        float sc  = gam[c] * rsqrtf(var + EPSBN);
        g_scale[c] = sc;
        g_shift[c] = bet[c] - mu * sc;
    }
}

// ---------------- finalize: affine extreme + relu -> out (B,C2,M) -------------
__global__ void k_finalmax(float* __restrict__ out) {
    const int t = blockIdx.x * 256 + threadIdx.x;
    const int m = t & 1023;
    const int c = (t >> 10) & 127;
    const int b = t >> 17;
    const int qidx = (b << 10) + m;
    const float sc = g_scale[c], sh = g_shift[c];
    float ext = (sc >= 0.0f) ? g_hmax[(size_t)c*NQ + qidx] : g_hmin[(size_t)c*NQ + qidx];
    float v = fmaxf(fmaf(ext, sc, sh), 0.0f);
    out[(size_t)BB*MM*3 + (((size_t)b*C2 + c) << 10) + m] = v;
}

// ---------------- launch --------------------------------------------------------
extern "C" void kernel_launch(void* const* d_in, const int* in_sizes, int n_in,
                              void* d_out, int out_size) {
    const float* p   = (const float*)d_in[0];
    const float* q   = (const float*)d_in[1];
    const float* x   = (const float*)d_in[2];
    const float* W0  = (const float*)d_in[3];
    const float* b0  = (const float*)d_in[4];
    const float* g0  = (const float*)d_in[5];
    const float* be0 = (const float*)d_in[6];
    const float* W1  = (const float*)d_in[7];
    const float* b1  = (const float*)d_in[8];
    const float* g1  = (const float*)d_in[9];
    const float* be1 = (const float*)d_in[10];
    const float* W2  = (const float*)d_in[11];
    const float* b2  = (const float*)d_in[12];
    const float* g2  = (const float*)d_in[13];
    const float* be2 = (const float*)d_in[14];
    float* out = (float*)d_out;

    float *h0p, *h1p;
    cudaGetSymbolAddress((void**)&h0p, g_h0);
    cudaGetSymbolAddress((void**)&h1p, g_h1);

    const int bq_smem = NN*3*4 + 8*KK*4;
    const int m0_smem = 2*80*256 + 2*64*256 + 64*4;               // 74240
    const int m1_smem = 2*64*128*2 + 2*64*64*2 + (64+128)*4 + 2*8*64*4;
    const int m2_smem = 2*64*128*2 + 2*128*64*2 + (128+128)*4 + 2*8*128*4;
    cudaFuncSetAttribute(k_ballquery, cudaFuncAttributeMaxDynamicSharedMemorySize, bq_smem);
    cudaFuncSetAttribute(k_mma0, cudaFuncAttributeMaxDynamicSharedMemorySize, m0_smem);
    cudaFuncSetAttribute((const void*)k_mma<64,false>,  cudaFuncAttributeMaxDynamicSharedMemorySize, m1_smem);
    cudaFuncSetAttribute((const void*)k_mma<128,true>,  cudaFuncAttributeMaxDynamicSharedMemorySize, m2_smem);

    k_transpose<<<dim3(NN/32, CF/32, BB), dim3(32, 8)>>>(x);
    k_copyq<<<(BB*MM*3)/256, 256>>>(q, out);
    k_ballquery<<<dim3(MM/8, BB), 256, bq_smem>>>(p, q);

    k_mma0<<<NMB, 256, m0_smem>>>(p, q, W0, b0);
    k_reduce2<<<C0, 256>>>(g0, be0, PSW);

    k_mma<64,false><<<NMB, 256, m1_smem>>>(h0p, h1p, W1, b1);
    k_reduce2<<<C1, 256>>>(g1, be1, PSW);

    k_mma<128,true><<<NMB, 256, m2_smem>>>(h1p, nullptr, W2, b2);
    k_reduce2<<<C2, 256>>>(g2, be2, PSW);

    k_finalmax<<<(BB*C2*MM)/256, 256>>>(out);
}